// round 12
// baseline (speedup 1.0000x reference)
#include <cuda_runtime.h>
#include <math.h>
#include <stdint.h>

#define NN 50000
#define EE 150000
#define RR 3
#define LL 2
#define HH 512
#define NHEADS 8
#define DHH 64
#define NCLSS 23
#define NNHH ((size_t)NN * HH)

// ---------------- scratch (device globals; no allocs allowed) ----------------
__device__ float g_h[NNHH];
__device__ unsigned g_h32[NNHH];
__device__ float g_go[(size_t)9 * NNHH];  // per-layer GEMM outputs: z = r*3 + {conv,gat,skip}
__device__ unsigned g_stk32[(size_t)NN * RR * HH];
__device__ float g_q[(size_t)NN * RR * HH];
__device__ float g_k[(size_t)NN * RR * HH];
__device__ float g_v[(size_t)NN * RR * HH];
__device__ unsigned g_w32[(size_t)24 * HH * HH];  // tf32: Wc(6) Wg(6) Ws(6) Wq(2) Wk(2) Wv(2)
__device__ float g_rdo[(size_t)RR * NN];
__device__ float g_rdi[(size_t)RR * NN];
__device__ float g_el[(size_t)RR * NN * NHEADS];
__device__ float g_er[(size_t)RR * NN * NHEADS];
// CSR (dst-indexed) per relation
__device__ int g_cnt[(size_t)RR * NN];
__device__ int g_cur[(size_t)RR * NN];
__device__ int g_off[(size_t)RR * (NN + 1)];
__device__ int g_eid[(size_t)RR * EE];

// ---------------- helpers ----------------
__device__ __forceinline__ float block_reduce_sum_128(float val) {
    __shared__ float sh[32];
    __syncthreads();
    int lane = threadIdx.x & 31;
    int wid = threadIdx.x >> 5;
#pragma unroll
    for (int o = 16; o > 0; o >>= 1) val += __shfl_xor_sync(0xffffffffu, val, o);
    if (lane == 0) sh[wid] = val;
    __syncthreads();
    if (wid == 0) {
        float v = (lane < (blockDim.x >> 5)) ? sh[lane] : 0.0f;
#pragma unroll
        for (int o = 16; o > 0; o >>= 1) v += __shfl_xor_sync(0xffffffffu, v, o);
        if (lane == 0) sh[0] = v;
    }
    __syncthreads();
    return sh[0];
}

__device__ __forceinline__ unsigned f2tf32(float x) {
    unsigned r;
    asm("cvt.rna.tf32.f32 %0, %1;" : "=r"(r) : "f"(x));
    return r;
}

__device__ __forceinline__ void mma_tf32(float* d, const unsigned* a, const unsigned* b) {
    asm volatile(
        "mma.sync.aligned.m16n8k8.row.col.f32.tf32.tf32.f32 "
        "{%0,%1,%2,%3}, {%4,%5,%6,%7}, {%8,%9}, {%0,%1,%2,%3};"
        : "+f"(d[0]), "+f"(d[1]), "+f"(d[2]), "+f"(d[3])
        : "r"(a[0]), "r"(a[1]), "r"(a[2]), "r"(a[3]), "r"(b[0]), "r"(b[1]));
}

__device__ __forceinline__ void cp16(void* smem_dst, const void* gmem_src, bool pred) {
    unsigned saddr = (unsigned)__cvta_generic_to_shared(smem_dst);
    int sz = pred ? 16 : 0;
    asm volatile("cp.async.cg.shared.global [%0], [%1], 16, %2;\n"
                 :: "r"(saddr), "l"(gmem_src), "r"(sz));
}
__device__ __forceinline__ void cp_commit() {
    asm volatile("cp.async.commit_group;\n");
}
template <int N>
__device__ __forceinline__ void cp_wait() {
    asm volatile("cp.async.wait_group %0;\n" :: "n"(N));
}

// ---------------- conversion kernels ----------------
__global__ void cvt_tf32_vec(const float4* __restrict__ in, uint4* __restrict__ out,
                             int n4) {
    int i = blockIdx.x * blockDim.x + threadIdx.x;
    if (i < n4) {
        float4 v = in[i];
        uint4 o;
        o.x = f2tf32(v.x); o.y = f2tf32(v.y); o.z = f2tf32(v.z); o.w = f2tf32(v.w);
        out[i] = o;
    }
}

// ---------------- degree + CSR build ----------------
__global__ void degree_count(const int* __restrict__ src, const int* __restrict__ dst,
                             float* __restrict__ rdo, float* __restrict__ rdi,
                             int* __restrict__ cnt) {
    int idx = blockIdx.x * blockDim.x + threadIdx.x;
    if (idx >= RR * EE) return;
    int r = idx / EE;
    int d = dst[idx];
    atomicAdd(&rdo[(size_t)r * NN + src[idx]], 1.0f);
    atomicAdd(&rdi[(size_t)r * NN + d], 1.0f);
    atomicAdd(&cnt[(size_t)r * NN + d], 1);
}

__global__ void degree_finalize(float* __restrict__ p, int n) {
    int idx = blockIdx.x * blockDim.x + threadIdx.x;
    if (idx < n) p[idx] = rsqrtf(fmaxf(p[idx], 1.0f));
}

__global__ __launch_bounds__(1024) void scan_offsets(const int* __restrict__ cnt,
                                                     int* __restrict__ off) {
    int r = blockIdx.x;
    const int* c = cnt + (size_t)r * NN;
    int* o = off + (size_t)r * (NN + 1);
    __shared__ int warp_sums[32];
    __shared__ int s_carry;
    if (threadIdx.x == 0) s_carry = 0;
    __syncthreads();
    int lane = threadIdx.x & 31;
    int w = threadIdx.x >> 5;
    for (int base = 0; base < NN; base += 1024) {
        int idx = base + threadIdx.x;
        int val = (idx < NN) ? c[idx] : 0;
        int x = val;
#pragma unroll
        for (int s = 1; s < 32; s <<= 1) {
            int y = __shfl_up_sync(0xffffffffu, x, s);
            if (lane >= s) x += y;
        }
        if (lane == 31) warp_sums[w] = x;
        __syncthreads();
        if (w == 0) {
            int y = warp_sums[lane];
#pragma unroll
            for (int s = 1; s < 32; s <<= 1) {
                int z = __shfl_up_sync(0xffffffffu, y, s);
                if (lane >= s) y += z;
            }
            warp_sums[lane] = y;
        }
        __syncthreads();
        int excl = x - val + ((w > 0) ? warp_sums[w - 1] : 0) + s_carry;
        if (idx < NN) o[idx] = excl;
        int chunk_total = warp_sums[31];
        __syncthreads();
        if (threadIdx.x == 0) s_carry += chunk_total;
        __syncthreads();
    }
    if (threadIdx.x == 0) o[NN] = s_carry;
}

__global__ void build_adj(const int* __restrict__ dst, const int* __restrict__ off,
                          int* __restrict__ cur, int* __restrict__ eid) {
    int idx = blockIdx.x * blockDim.x + threadIdx.x;
    if (idx >= RR * EE) return;
    int r = idx / EE;
    int e = idx - r * EE;
    int d = dst[idx];
    int pos = atomicAdd(&cur[(size_t)r * NN + d], 1);
    eid[(size_t)r * EE + off[(size_t)r * (NN + 1) + d] + pos] = e;
}

// ---------------- batched TF32 tensor-core GEMM (z weights, shared A) ---------
// C_z[M,512] = A[M,512] @ W_z[512,512] (* rs_z[row]) (+ b_z[col]), z = blockIdx.z
// 2-stage cp.async (71.7KB smem -> 2 CTAs/SM; 3-stage halves occupancy, R10).
#define A_STRIDE 36   // words
#define B_STRIDE 136  // words
#define AS_WORDS (128 * A_STRIDE)
#define BS_WORDS (32 * B_STRIDE)
#define GEMM_SMEM ((2 * AS_WORDS + 2 * BS_WORDS) * 4)

struct G3 {
    const unsigned* W[3];
    float* C[3];
    const float* rs[3];
    const float* b[3];
};

__global__ __launch_bounds__(256) void tf32gemm3(
    const unsigned* __restrict__ A, G3 args, int M) {
    extern __shared__ unsigned sm[];
    unsigned* As = sm;                 // 2 stages
    unsigned* Bs = sm + 2 * AS_WORDS;  // 2 stages

    const int z = blockIdx.z;
    const unsigned* W = args.W[z];
    const int bm = blockIdx.y * 128;
    const int bn = blockIdx.x * 128;
    const int tid = threadIdx.x;
    const int warp = tid >> 5;
    const int lane = tid & 31;
    const int g = lane >> 2;
    const int t = lane & 3;
    const int wm = (warp >> 1) * 32;
    const int wn = (warp & 1) * 64;

    float acc[2][8][4];
#pragma unroll
    for (int i = 0; i < 2; i++)
#pragma unroll
        for (int j = 0; j < 8; j++)
#pragma unroll
            for (int q = 0; q < 4; q++) acc[i][j][q] = 0.0f;

    int a_row[4], a_c4[4], b_kk[4], b_n4[4];
#pragma unroll
    for (int i = 0; i < 4; i++) {
        int slot = tid + i * 256;
        a_row[i] = slot >> 3;
        a_c4[i] = slot & 7;
        b_kk[i] = slot >> 5;
        b_n4[i] = slot & 31;
    }

#define LOAD_TILE(k0, st)                                                          \
    do {                                                                           \
        unsigned* as = As + (st)*AS_WORDS;                                         \
        unsigned* bs = Bs + (st)*BS_WORDS;                                         \
        _Pragma("unroll") for (int i = 0; i < 4; i++) {                            \
            int gr = bm + a_row[i];                                                \
            cp16(as + a_row[i] * A_STRIDE + a_c4[i] * 4,                           \
                 A + (size_t)gr * 512 + (k0) + a_c4[i] * 4, gr < M);               \
            cp16(bs + b_kk[i] * B_STRIDE + b_n4[i] * 4,                            \
                 W + (size_t)((k0) + b_kk[i]) * 512 + bn + b_n4[i] * 4, true);     \
        }                                                                          \
    } while (0)

    LOAD_TILE(0, 0);
    cp_commit();
    int stage = 0;
#pragma unroll 1
    for (int it = 0; it < 16; it++) {
        if (it + 1 < 16) {
            LOAD_TILE((it + 1) * 32, stage ^ 1);
            cp_commit();
            cp_wait<1>();
        } else {
            cp_wait<0>();
        }
        __syncthreads();
        const unsigned* as = As + stage * AS_WORDS;
        const unsigned* bs = Bs + stage * BS_WORDS;
#pragma unroll
        for (int ks = 0; ks < 4; ks++) {
            const int k = ks * 8;
            unsigned afr[2][4];
#pragma unroll
            for (int mt = 0; mt < 2; mt++) {
                int r = wm + mt * 16 + g;
                afr[mt][0] = as[r * A_STRIDE + k + t];
                afr[mt][1] = as[(r + 8) * A_STRIDE + k + t];
                afr[mt][2] = as[r * A_STRIDE + k + t + 4];
                afr[mt][3] = as[(r + 8) * A_STRIDE + k + t + 4];
            }
            unsigned bfr[8][2];
#pragma unroll
            for (int nt = 0; nt < 8; nt++) {
                int n = wn + nt * 8 + g;
                bfr[nt][0] = bs[(k + t) * B_STRIDE + n];
                bfr[nt][1] = bs[(k + t + 4) * B_STRIDE + n];
            }
#pragma unroll
            for (int mt = 0; mt < 2; mt++)
#pragma unroll
                for (int nt = 0; nt < 8; nt++)
                    mma_tf32(acc[mt][nt], afr[mt], bfr[nt]);
        }
        __syncthreads();
        stage ^= 1;
    }

    float* C = args.C[z];
    const float* rowscale = args.rs[z];
    const float* bias = args.b[z];
#pragma unroll
    for (int mt = 0; mt < 2; mt++) {
        int r0 = bm + wm + mt * 16 + g;
        int r1 = r0 + 8;
        float s0 = 1.0f, s1 = 1.0f;
        if (rowscale) {
            if (r0 < M) s0 = rowscale[r0];
            if (r1 < M) s1 = rowscale[r1];
        }
#pragma unroll
        for (int nt = 0; nt < 8; nt++) {
            int c = bn + wn + nt * 8 + t * 2;
            float b0 = 0.0f, b1 = 0.0f;
            if (bias) { b0 = bias[c]; b1 = bias[c + 1]; }
            if (r0 < M) {
                float2 v = make_float2(acc[mt][nt][0] * s0 + b0,
                                       acc[mt][nt][1] * s0 + b1);
                *(float2*)(C + (size_t)r0 * 512 + c) = v;
            }
            if (r1 < M) {
                float2 v = make_float2(acc[mt][nt][2] * s1 + b0,
                                       acc[mt][nt][3] * s1 + b1);
                *(float2*)(C + (size_t)r1 * 512 + c) = v;
            }
        }
    }
}

// ---------------- LN core ----------------
__device__ __forceinline__ float4 ln_elu_core4(
    float4 v, const float* __restrict__ gamma, const float* __restrict__ beta) {
    int t = threadIdx.x;
    float sum = v.x + v.y + v.z + v.w;
    sum = block_reduce_sum_128(sum);
    float u = sum * (1.0f / HH);
    float dx = v.x - u, dy = v.y - u, dz = v.z - u, dw = v.w - u;
    float var = dx * dx + dy * dy + dz * dz + dw * dw;
    var = block_reduce_sum_128(var) * (1.0f / HH);
    float inv = rsqrtf(var + 1e-12f);
    float4 ga = ((const float4*)gamma)[t];
    float4 be = ((const float4*)beta)[t];
    float y0 = ga.x * dx * inv + be.x;
    float y1 = ga.y * dy * inv + be.y;
    float y2 = ga.z * dz * inv + be.z;
    float y3 = ga.w * dw * inv + be.w;
    y0 = (y0 > 0.0f) ? y0 : (expf(y0) - 1.0f);
    y1 = (y1 > 0.0f) ? y1 : (expf(y1) - 1.0f);
    y2 = (y2 > 0.0f) ? y2 : (expf(y2) - 1.0f);
    y3 = (y3 > 0.0f) ? y3 : (expf(y3) - 1.0f);
    return make_float4(y0, y1, y2, y3);
}

// ---------------- mega-fused per-node branch kernel (single relation) ---------
// All pointers pre-offset for the relation by the host.
__global__ __launch_bounds__(128) void fused_branches(
    const int* __restrict__ eid, const int* __restrict__ off,
    const int* __restrict__ src, const float* __restrict__ go_r,
    const float* __restrict__ el, const float* __restrict__ er,
    const float* __restrict__ rdi,
    const float* __restrict__ bc, const float* __restrict__ gc,
    const float* __restrict__ bec,
    const float* __restrict__ bg, const float* __restrict__ gg,
    const float* __restrict__ beg,
    const float* __restrict__ bs_, const float* __restrict__ gs,
    const float* __restrict__ bes,
    unsigned* __restrict__ out32) {
    const int n = blockIdx.x;
    const float* Xc = go_r;
    const float* f = go_r + NNHH;
    const float* Xs = go_r + 2 * NNHH;

    int p0 = off[n], p1 = off[n + 1];
    int t = threadIdx.x;
    int h = t >> 4;

    __shared__ float sh_m[NHEADS], sh_invs[NHEADS];
    if (t < NHEADS) {
        float ern = er[n * NHEADS + t];
        float mx = -INFINITY;
        for (int p = p0; p < p1; p++) {
            float x = el[src[eid[p]] * NHEADS + t] + ern;
            x = (x > 0.0f) ? x : 0.2f * x;
            mx = fmaxf(mx, x);
        }
        float s = 0.0f;
        for (int p = p0; p < p1; p++) {
            float x = el[src[eid[p]] * NHEADS + t] + ern;
            x = (x > 0.0f) ? x : 0.2f * x;
            s += expf(x - mx);
        }
        sh_m[t] = mx;
        sh_invs[t] = (s > 0.0f) ? (1.0f / s) : 1.0f;
    }
    __syncthreads();

    float mh = sh_m[h];
    float invs = sh_invs[h];
    float ern = er[n * NHEADS + h];

    float4 ac = make_float4(0.f, 0.f, 0.f, 0.f);
    float4 ag = make_float4(0.f, 0.f, 0.f, 0.f);
    for (int p = p0; p < p1; p++) {
        int e = eid[p];
        int sn = src[e];
        float4 rc = ((const float4*)(Xc + (size_t)sn * HH))[t];
        float4 rg = ((const float4*)(f + (size_t)sn * HH))[t];
        float x = el[sn * NHEADS + h] + ern;
        x = (x > 0.0f) ? x : 0.2f * x;
        float a = expf(x - mh) * invs;
        ac.x += rc.x; ac.y += rc.y; ac.z += rc.z; ac.w += rc.w;
        ag.x += a * rg.x; ag.y += a * rg.y; ag.z += a * rg.z; ag.w += a * rg.w;
    }

    float sc = rdi[n];
    float4 bb = ((const float4*)bc)[t];
    float4 v = make_float4(ac.x * sc + bb.x, ac.y * sc + bb.y,
                           ac.z * sc + bb.z, ac.w * sc + bb.w);
    float4 y = ln_elu_core4(v, gc, bec);
    float rx = y.x, ry = y.y, rz = y.z, rw = y.w;

    bb = ((const float4*)bg)[t];
    v = make_float4(ag.x + bb.x, ag.y + bb.y, ag.z + bb.z, ag.w + bb.w);
    y = ln_elu_core4(v, gg, beg);
    rx += y.x; ry += y.y; rz += y.z; rw += y.w;

    float4 xs = ((const float4*)(Xs + (size_t)n * HH))[t];
    bb = ((const float4*)bs_)[t];
    v = make_float4(xs.x + bb.x, xs.y + bb.y, xs.z + bb.z, xs.w + bb.w);
    y = ln_elu_core4(v, gs, bes);
    rx += y.x; ry += y.y; rz += y.z; rw += y.w;

    uint4 o;
    o.x = f2tf32(rx); o.y = f2tf32(ry); o.z = f2tf32(rz); o.w = f2tf32(rw);
    ((uint4*)(out32 + (size_t)n * (RR * HH)))[t] = o;
}

// ---------------- GAT attn-score precompute (single relation) ----------------
__global__ void gat_el_er(const float* __restrict__ f,
                          const float* __restrict__ al_r,
                          const float* __restrict__ ar_r,
                          float* __restrict__ el, float* __restrict__ er) {
    int idx = blockIdx.x * blockDim.x + threadIdx.x;
    if (idx >= NN * NHEADS) return;
    int n = idx >> 3;
    int hh = idx & 7;
    const float* fr = f + (size_t)n * HH + hh * DHH;
    const float* a1 = al_r + hh * DHH;
    const float* a2 = ar_r + hh * DHH;
    float s1 = 0.0f, s2 = 0.0f;
#pragma unroll 8
    for (int d = 0; d < DHH; d++) {
        float fv = fr[d];
        s1 += fv * a1[d];
        s2 += fv * a2[d];
    }
    el[idx] = s1;
    er[idx] = s2;
}

// ---------------- relation MHA (3 tokens) + mean ----------------
__global__ __launch_bounds__(256) void mha_mean(
    const float* __restrict__ q, const float* __restrict__ k,
    const float* __restrict__ v, float* __restrict__ out,
    unsigned* __restrict__ out32) {
    int n = blockIdx.x;
    int hd = threadIdx.x >> 5;
    int lane = threadIdx.x & 31;
    size_t base = (size_t)n * RR * HH + hd * DHH;
    float qa[RR], qb[RR], ka[RR], kb[RR], va[RR], vb[RR];
#pragma unroll
    for (int r = 0; r < RR; r++) {
        size_t off = base + (size_t)r * HH;
        qa[r] = q[off + lane];
        qb[r] = q[off + lane + 32];
        ka[r] = k[off + lane];
        kb[r] = k[off + lane + 32];
        va[r] = v[off + lane];
        vb[r] = v[off + lane + 32];
    }
    float sc[RR][RR];
#pragma unroll
    for (int r = 0; r < RR; r++)
#pragma unroll
        for (int t = 0; t < RR; t++) {
            float p = qa[r] * ka[t] + qb[r] * kb[t];
#pragma unroll
            for (int o = 16; o > 0; o >>= 1) p += __shfl_xor_sync(0xffffffffu, p, o);
            sc[r][t] = p * 0.125f;
        }
    float w0 = 0.0f, w1 = 0.0f, w2 = 0.0f;
#pragma unroll
    for (int r = 0; r < RR; r++) {
        float mx = fmaxf(sc[r][0], fmaxf(sc[r][1], sc[r][2]));
        float e0 = expf(sc[r][0] - mx);
        float e1 = expf(sc[r][1] - mx);
        float e2 = expf(sc[r][2] - mx);
        float inv = 1.0f / (e0 + e1 + e2);
        w0 += e0 * inv;
        w1 += e1 * inv;
        w2 += e2 * inv;
    }
    const float third = 1.0f / 3.0f;
    float oa = (w0 * va[0] + w1 * va[1] + w2 * va[2]) * third;
    float ob = (w0 * vb[0] + w1 * vb[1] + w2 * vb[2]) * third;
    size_t o0 = (size_t)n * HH + hd * DHH + lane;
    out[o0] = oa;
    out[o0 + 32] = ob;
    out32[o0] = f2tf32(oa);
    out32[o0 + 32] = f2tf32(ob);
}

// ---------------- classifier ----------------
__global__ void classify(const float* __restrict__ h, const float* __restrict__ W,
                         const float* __restrict__ b, float* __restrict__ out) {
    int idx = blockIdx.x * blockDim.x + threadIdx.x;
    if (idx >= NN * NCLSS) return;
    int n = idx / NCLSS;
    int c = idx % NCLSS;
    const float* hr = h + (size_t)n * HH;
    float sum = b[c];
#pragma unroll 8
    for (int j = 0; j < HH; j++) sum += hr[j] * W[j * NCLSS + c];
    out[idx] = sum;
}

// ---------------- launch ----------------
extern "C" void kernel_launch(void* const* d_in, const int* in_sizes, int n_in,
                              void* d_out, int out_size) {
    const float* feature = (const float*)d_in[0];
    const int* src = (const int*)d_in[1];
    const int* dst = (const int*)d_in[2];
    const float* Wc = (const float*)d_in[3];
    const float* bc = (const float*)d_in[4];
    const float* gc = (const float*)d_in[5];
    const float* betac = (const float*)d_in[6];
    const float* Wg = (const float*)d_in[7];
    const float* bg = (const float*)d_in[8];
    const float* al = (const float*)d_in[9];
    const float* ar = (const float*)d_in[10];
    const float* gg = (const float*)d_in[11];
    const float* betag = (const float*)d_in[12];
    const float* Ws = (const float*)d_in[13];
    const float* bs = (const float*)d_in[14];
    const float* gs = (const float*)d_in[15];
    const float* betas = (const float*)d_in[16];
    const float* Wq = (const float*)d_in[17];
    const float* bq = (const float*)d_in[18];
    const float* Wk = (const float*)d_in[19];
    const float* bk = (const float*)d_in[20];
    const float* Wv = (const float*)d_in[21];
    const float* bv = (const float*)d_in[22];
    const float* Wout = (const float*)d_in[23];
    const float* bout = (const float*)d_in[24];
    float* out = (float*)d_out;

    float *p_h, *p_go, *p_q, *p_k, *p_v;
    float *p_rdo, *p_rdi, *p_el, *p_er;
    unsigned *p_h32, *p_stk32, *p_w32;
    int *p_cnt, *p_cur, *p_off, *p_eid;
    cudaGetSymbolAddress((void**)&p_h, g_h);
    cudaGetSymbolAddress((void**)&p_h32, g_h32);
    cudaGetSymbolAddress((void**)&p_go, g_go);
    cudaGetSymbolAddress((void**)&p_stk32, g_stk32);
    cudaGetSymbolAddress((void**)&p_q, g_q);
    cudaGetSymbolAddress((void**)&p_k, g_k);
    cudaGetSymbolAddress((void**)&p_v, g_v);
    cudaGetSymbolAddress((void**)&p_w32, g_w32);
    cudaGetSymbolAddress((void**)&p_rdo, g_rdo);
    cudaGetSymbolAddress((void**)&p_rdi, g_rdi);
    cudaGetSymbolAddress((void**)&p_el, g_el);
    cudaGetSymbolAddress((void**)&p_er, g_er);
    cudaGetSymbolAddress((void**)&p_cnt, g_cnt);
    cudaGetSymbolAddress((void**)&p_cur, g_cur);
    cudaGetSymbolAddress((void**)&p_off, g_off);
    cudaGetSymbolAddress((void**)&p_eid, g_eid);

    cudaFuncSetAttribute(tf32gemm3, cudaFuncAttributeMaxDynamicSharedMemorySize,
                         GEMM_SMEM);

    const size_t WHH = (size_t)HH * HH;
    unsigned* w32_Wc = p_w32;
    unsigned* w32_Wg = p_w32 + 6 * WHH;
    unsigned* w32_Ws = p_w32 + 12 * WHH;
    unsigned* w32_Wq = p_w32 + 18 * WHH;
    unsigned* w32_Wk = p_w32 + 20 * WHH;
    unsigned* w32_Wv = p_w32 + 22 * WHH;

    // streams + events (fork/join inside graph capture)
    cudaStream_t s0 = 0, s1, s2;
    cudaStreamCreateWithFlags(&s1, cudaStreamNonBlocking);
    cudaStreamCreateWithFlags(&s2, cudaStreamNonBlocking);
    cudaEvent_t ev[10];
    for (int i = 0; i < 10; i++)
        cudaEventCreateWithFlags(&ev[i], cudaEventDisableTiming);
    cudaEvent_t evStart = ev[0], evCSR = ev[1];
    // per-layer: fork ev[2+l], joins ev[4+2l], ev[5+2l]

    cudaEventRecord(evStart, s0);
    cudaStreamWaitEvent(s1, evStart, 0);

    // s1: degree + CSR (independent of cvt)
    cudaMemsetAsync(p_rdo, 0, (size_t)RR * NN * sizeof(float), s1);
    cudaMemsetAsync(p_rdi, 0, (size_t)RR * NN * sizeof(float), s1);
    cudaMemsetAsync(p_cnt, 0, (size_t)RR * NN * sizeof(int), s1);
    cudaMemsetAsync(p_cur, 0, (size_t)RR * NN * sizeof(int), s1);
    degree_count<<<(RR * EE + 255) / 256, 256, 0, s1>>>(src, dst, p_rdo, p_rdi,
                                                        p_cnt);
    degree_finalize<<<(RR * NN + 255) / 256, 256, 0, s1>>>(p_rdo, RR * NN);
    degree_finalize<<<(RR * NN + 255) / 256, 256, 0, s1>>>(p_rdi, RR * NN);
    scan_offsets<<<RR, 1024, 0, s1>>>(p_cnt, p_off);
    build_adj<<<(RR * EE + 255) / 256, 256, 0, s1>>>(dst, p_off, p_cur, p_eid);
    cudaEventRecord(evCSR, s1);

    // s0: convert weights + feature to tf32
    {
        int n4 = (int)(6 * WHH / 4);
        int blocks = (n4 + 255) / 256;
        cvt_tf32_vec<<<blocks, 256, 0, s0>>>((const float4*)Wc, (uint4*)w32_Wc, n4);
        cvt_tf32_vec<<<blocks, 256, 0, s0>>>((const float4*)Wg, (uint4*)w32_Wg, n4);
        cvt_tf32_vec<<<blocks, 256, 0, s0>>>((const float4*)Ws, (uint4*)w32_Ws, n4);
        int n4q = (int)(2 * WHH / 4);
        int blocksq = (n4q + 255) / 256;
        cvt_tf32_vec<<<blocksq, 256, 0, s0>>>((const float4*)Wq, (uint4*)w32_Wq, n4q);
        cvt_tf32_vec<<<blocksq, 256, 0, s0>>>((const float4*)Wk, (uint4*)w32_Wk, n4q);
        cvt_tf32_vec<<<blocksq, 256, 0, s0>>>((const float4*)Wv, (uint4*)w32_Wv, n4q);
        int n4f = (int)(NNHH / 4);
        cvt_tf32_vec<<<(n4f + 255) / 256, 256, 0, s0>>>((const float4*)feature,
                                                        (uint4*)p_h32, n4f);
    }
    cudaStreamWaitEvent(s0, evCSR, 0);  // all relation chains need CSR/degrees

    const dim3 gemm_grid_n(4, (NN + 127) / 128, 3);
    const dim3 gemm_grid_nr(4, (NN * RR + 127) / 128, 3);
    const int nhd_blocks = (NN * NHEADS + 255) / 256;
    cudaStream_t sr[3] = {s0, s1, s2};

    for (int l = 0; l < LL; l++) {
        const size_t lbase = (size_t)l * RR;
        cudaEvent_t evFork = ev[2 + l];
        cudaEventRecord(evFork, s0);
        cudaStreamWaitEvent(s1, evFork, 0);
        cudaStreamWaitEvent(s2, evFork, 0);

        for (int r = 0; r < RR; r++) {
            const size_t lr = lbase + r;
            cudaStream_t st = sr[r];
            float* go_r = p_go + (size_t)r * 3 * NNHH;
            float* el_r = p_el + (size_t)r * NN * NHEADS;
            float* er_r = p_er + (size_t)r * NN * NHEADS;

            G3 a3;
            a3.W[0] = w32_Wc + lr * WHH;
            a3.W[1] = w32_Wg + lr * WHH;
            a3.W[2] = w32_Ws + lr * WHH;
            a3.C[0] = go_r;
            a3.C[1] = go_r + NNHH;
            a3.C[2] = go_r + 2 * NNHH;
            a3.rs[0] = p_rdo + (size_t)r * NN;
            a3.rs[1] = nullptr;
            a3.rs[2] = nullptr;
            a3.b[0] = nullptr;
            a3.b[1] = nullptr;
            a3.b[2] = nullptr;
            tf32gemm3<<<gemm_grid_n, 256, GEMM_SMEM, st>>>(p_h32, a3, NN);

            gat_el_er<<<nhd_blocks, 256, 0, st>>>(
                go_r + NNHH, al + lr * NHEADS * DHH, ar + lr * NHEADS * DHH,
                el_r, er_r);

            fused_branches<<<NN, 128, 0, st>>>(
                p_eid + (size_t)r * EE, p_off + (size_t)r * (NN + 1),
                src + (size_t)r * EE, go_r, el_r, er_r,
                p_rdi + (size_t)r * NN,
                bc + lr * HH, gc + lr * HH, betac + lr * HH,
                bg + lr * HH, gg + lr * HH, betag + lr * HH,
                bs + lr * HH, gs + lr * HH, betas + lr * HH,
                p_stk32 + (size_t)r * HH);
        }
        cudaEventRecord(ev[4 + 2 * l], s1);
        cudaEventRecord(ev[5 + 2 * l], s2);
        cudaStreamWaitEvent(s0, ev[4 + 2 * l], 0);
        cudaStreamWaitEvent(s0, ev[5 + 2 * l], 0);

        // ---- relation MHA: batched QKV GEMM on s0 ----
        G3 aq;
        aq.W[0] = w32_Wq + (size_t)l * WHH;
        aq.W[1] = w32_Wk + (size_t)l * WHH;
        aq.W[2] = w32_Wv + (size_t)l * WHH;
        aq.C[0] = p_q;
        aq.C[1] = p_k;
        aq.C[2] = p_v;
        aq.rs[0] = nullptr; aq.rs[1] = nullptr; aq.rs[2] = nullptr;
        aq.b[0] = bq + (size_t)l * HH;
        aq.b[1] = bk + (size_t)l * HH;
        aq.b[2] = bv + (size_t)l * HH;
        tf32gemm3<<<gemm_grid_nr, 256, GEMM_SMEM, s0>>>(p_stk32, aq, NN * RR);

        mha_mean<<<NN, 256, 0, s0>>>(p_q, p_k, p_v, p_h, p_h32);
    }

    classify<<<(NN * NCLSS + 255) / 256, 256, 0, s0>>>(p_h, Wout, bout, out);

    for (int i = 0; i < 10; i++) cudaEventDestroy(ev[i]);
    cudaStreamDestroy(s1);
    cudaStreamDestroy(s2);
}

// round 13
// speedup vs baseline: 1.4477x; 1.4477x over previous
#include <cuda_runtime.h>
#include <cuda_fp16.h>
#include <math.h>
#include <stdint.h>

#define NN 50000
#define EE 150000
#define RR 3
#define LL 2
#define HH 512
#define NHEADS 8
#define DHH 64
#define NCLSS 23
#define NNHH ((size_t)NN * HH)

// ---------------- scratch (device globals; no allocs allowed) ----------------
__device__ float g_h[NNHH];
__device__ __half g_h16[NNHH];
__device__ float g_go[(size_t)9 * NNHH];  // per-layer GEMM outputs
__device__ __half g_stk16[(size_t)NN * RR * HH];
__device__ float g_q[(size_t)NN * RR * HH];
__device__ float g_k[(size_t)NN * RR * HH];
__device__ float g_v[(size_t)NN * RR * HH];
__device__ __half g_w16[(size_t)24 * HH * HH];  // TRANSPOSED [N][K] f16 weights
__device__ float g_rdo[(size_t)RR * NN];
__device__ float g_rdi[(size_t)RR * NN];
__device__ float g_el[(size_t)RR * NN * NHEADS];
__device__ float g_er[(size_t)RR * NN * NHEADS];
// CSR (dst-indexed) per relation
__device__ int g_cnt[(size_t)RR * NN];
__device__ int g_cur[(size_t)RR * NN];
__device__ int g_off[(size_t)RR * (NN + 1)];
__device__ int g_eid[(size_t)RR * EE];

// ---------------- helpers ----------------
__device__ __forceinline__ float block_reduce_sum_128(float val) {
    __shared__ float sh[32];
    __syncthreads();
    int lane = threadIdx.x & 31;
    int wid = threadIdx.x >> 5;
#pragma unroll
    for (int o = 16; o > 0; o >>= 1) val += __shfl_xor_sync(0xffffffffu, val, o);
    if (lane == 0) sh[wid] = val;
    __syncthreads();
    if (wid == 0) {
        float v = (lane < (blockDim.x >> 5)) ? sh[lane] : 0.0f;
#pragma unroll
        for (int o = 16; o > 0; o >>= 1) v += __shfl_xor_sync(0xffffffffu, v, o);
        if (lane == 0) sh[0] = v;
    }
    __syncthreads();
    return sh[0];
}

__device__ __forceinline__ void mma_f16(float* d, const unsigned* a, const unsigned* b) {
    asm volatile(
        "mma.sync.aligned.m16n8k16.row.col.f32.f16.f16.f32 "
        "{%0,%1,%2,%3}, {%4,%5,%6,%7}, {%8,%9}, {%0,%1,%2,%3};"
        : "+f"(d[0]), "+f"(d[1]), "+f"(d[2]), "+f"(d[3])
        : "r"(a[0]), "r"(a[1]), "r"(a[2]), "r"(a[3]), "r"(b[0]), "r"(b[1]));
}

__device__ __forceinline__ void cp16(void* smem_dst, const void* gmem_src, bool pred) {
    unsigned saddr = (unsigned)__cvta_generic_to_shared(smem_dst);
    int sz = pred ? 16 : 0;
    asm volatile("cp.async.cg.shared.global [%0], [%1], 16, %2;\n"
                 :: "r"(saddr), "l"(gmem_src), "r"(sz));
}
__device__ __forceinline__ void cp_commit() {
    asm volatile("cp.async.commit_group;\n");
}
template <int N>
__device__ __forceinline__ void cp_wait() {
    asm volatile("cp.async.wait_group %0;\n" :: "n"(N));
}

// ---------------- conversion kernels ----------------
__global__ void cvt_f16_vec(const float4* __restrict__ in,
                            __half2* __restrict__ out, int n4) {
    int i = blockIdx.x * blockDim.x + threadIdx.x;
    if (i < n4) {
        float4 v = in[i];
        out[2 * i] = __floats2half2_rn(v.x, v.y);
        out[2 * i + 1] = __floats2half2_rn(v.z, v.w);
    }
}

// transpose W[K,N] -> Wt[N,K] f16; grid (16,16,nmat), block (32,8)
__global__ void transpose_cvt16(const float* __restrict__ in,
                                __half* __restrict__ out) {
    __shared__ float tile[32][33];
    const float* A = in + (size_t)blockIdx.z * HH * HH;
    __half* O = out + (size_t)blockIdx.z * HH * HH;
    int x = blockIdx.x * 32 + threadIdx.x;
    int y0 = blockIdx.y * 32 + threadIdx.y;
#pragma unroll
    for (int i = 0; i < 32; i += 8)
        tile[threadIdx.y + i][threadIdx.x] = A[(size_t)(y0 + i) * HH + x];
    __syncthreads();
    int ox = blockIdx.y * 32 + threadIdx.x;
    int oy0 = blockIdx.x * 32 + threadIdx.y;
#pragma unroll
    for (int i = 0; i < 32; i += 8)
        O[(size_t)(oy0 + i) * HH + ox] =
            __float2half_rn(tile[threadIdx.x][threadIdx.y + i]);
}

// ---------------- degree + CSR build ----------------
__global__ void degree_count(const int* __restrict__ src, const int* __restrict__ dst,
                             float* __restrict__ rdo, float* __restrict__ rdi,
                             int* __restrict__ cnt) {
    int idx = blockIdx.x * blockDim.x + threadIdx.x;
    if (idx >= RR * EE) return;
    int r = idx / EE;
    int d = dst[idx];
    atomicAdd(&rdo[(size_t)r * NN + src[idx]], 1.0f);
    atomicAdd(&rdi[(size_t)r * NN + d], 1.0f);
    atomicAdd(&cnt[(size_t)r * NN + d], 1);
}

__global__ void degree_finalize(float* __restrict__ p, int n) {
    int idx = blockIdx.x * blockDim.x + threadIdx.x;
    if (idx < n) p[idx] = rsqrtf(fmaxf(p[idx], 1.0f));
}

__global__ __launch_bounds__(1024) void scan_offsets(const int* __restrict__ cnt,
                                                     int* __restrict__ off) {
    int r = blockIdx.x;
    const int* c = cnt + (size_t)r * NN;
    int* o = off + (size_t)r * (NN + 1);
    __shared__ int warp_sums[32];
    __shared__ int s_carry;
    if (threadIdx.x == 0) s_carry = 0;
    __syncthreads();
    int lane = threadIdx.x & 31;
    int w = threadIdx.x >> 5;
    for (int base = 0; base < NN; base += 1024) {
        int idx = base + threadIdx.x;
        int val = (idx < NN) ? c[idx] : 0;
        int x = val;
#pragma unroll
        for (int s = 1; s < 32; s <<= 1) {
            int y = __shfl_up_sync(0xffffffffu, x, s);
            if (lane >= s) x += y;
        }
        if (lane == 31) warp_sums[w] = x;
        __syncthreads();
        if (w == 0) {
            int y = warp_sums[lane];
#pragma unroll
            for (int s = 1; s < 32; s <<= 1) {
                int z = __shfl_up_sync(0xffffffffu, y, s);
                if (lane >= s) y += z;
            }
            warp_sums[lane] = y;
        }
        __syncthreads();
        int excl = x - val + ((w > 0) ? warp_sums[w - 1] : 0) + s_carry;
        if (idx < NN) o[idx] = excl;
        int chunk_total = warp_sums[31];
        __syncthreads();
        if (threadIdx.x == 0) s_carry += chunk_total;
        __syncthreads();
    }
    if (threadIdx.x == 0) o[NN] = s_carry;
}

__global__ void build_adj(const int* __restrict__ dst, const int* __restrict__ off,
                          int* __restrict__ cur, int* __restrict__ eid) {
    int idx = blockIdx.x * blockDim.x + threadIdx.x;
    if (idx >= RR * EE) return;
    int r = idx / EE;
    int e = idx - r * EE;
    int d = dst[idx];
    int pos = atomicAdd(&cur[(size_t)r * NN + d], 1);
    eid[(size_t)r * EE + off[(size_t)r * (NN + 1) + d] + pos] = e;
}

// ---------------- batched FP16 tensor-core GEMM (up to 9 weights, shared A) ---
// C_z[M,512] = A[M,512] @ Wt_z[512,512]^T (* rs_z[row]) (+ b_z[col])
// A f16 row-major [M,K]; Wt f16 [N,K] (transposed). m16n8k16.f32.f16.f16.f32.
// BK=64, 2-stage cp.async, 73.7KB smem -> 2 CTAs/SM (do NOT deepen: R10).
#define AW 36  // words per 64-half row (32 data + 4 pad)
#define AS_WORDS (128 * AW)
#define BS_WORDS (128 * AW)
#define GEMM_SMEM ((2 * AS_WORDS + 2 * BS_WORDS) * 4)

struct G9 {
    const __half* W[9];
    float* C[9];
    const float* rs[9];
    const float* b[9];
};

__global__ __launch_bounds__(256) void f16gemm9(
    const __half* __restrict__ A, G9 args, int M) {
    extern __shared__ unsigned sm[];
    unsigned* As = sm;                 // 2 stages
    unsigned* Bs = sm + 2 * AS_WORDS;  // 2 stages

    const int z = blockIdx.z;
    const __half* Wt = args.W[z];
    const int bm = blockIdx.y * 128;
    const int bn = blockIdx.x * 128;
    const int tid = threadIdx.x;
    const int warp = tid >> 5;
    const int lane = tid & 31;
    const int g = lane >> 2;
    const int t = lane & 3;
    const int wm = (warp >> 1) * 32;
    const int wn = (warp & 1) * 64;

    float acc[2][8][4];
#pragma unroll
    for (int i = 0; i < 2; i++)
#pragma unroll
        for (int j = 0; j < 8; j++)
#pragma unroll
            for (int q = 0; q < 4; q++) acc[i][j][q] = 0.0f;

    int l_row[4], l_c[4];
#pragma unroll
    for (int i = 0; i < 4; i++) {
        int slot = tid + i * 256;
        l_row[i] = slot >> 3;
        l_c[i] = slot & 7;
    }

// K-block of 64 halves; A rows 128, B n-rows 128, 8 chunks of 8 halves each
#define LOAD_TILE(k0, st)                                                          \
    do {                                                                           \
        unsigned* as = As + (st)*AS_WORDS;                                         \
        unsigned* bs = Bs + (st)*BS_WORDS;                                         \
        _Pragma("unroll") for (int i = 0; i < 4; i++) {                            \
            int row = l_row[i], c = l_c[i];                                        \
            int gr = bm + row;                                                     \
            cp16(as + row * AW + c * 4,                                            \
                 A + (size_t)gr * 512 + (k0) + c * 8, gr < M);                     \
            cp16(bs + row * AW + c * 4,                                            \
                 Wt + (size_t)(bn + row) * 512 + (k0) + c * 8, true);              \
        }                                                                          \
    } while (0)

    LOAD_TILE(0, 0);
    cp_commit();
    int stage = 0;
#pragma unroll 1
    for (int it = 0; it < 8; it++) {
        if (it + 1 < 8) {
            LOAD_TILE((it + 1) * 64, stage ^ 1);
            cp_commit();
            cp_wait<1>();
        } else {
            cp_wait<0>();
        }
        __syncthreads();
        const unsigned* as = As + stage * AS_WORDS;
        const unsigned* bs = Bs + stage * BS_WORDS;
#pragma unroll
        for (int ks = 0; ks < 4; ks++) {
            const int pb = ks * 8;  // pair-base (16 halves = 8 words per step)
            unsigned afr[2][4];
#pragma unroll
            for (int mt = 0; mt < 2; mt++) {
                int r = wm + mt * 16 + g;
                afr[mt][0] = as[r * AW + pb + t];
                afr[mt][1] = as[(r + 8) * AW + pb + t];
                afr[mt][2] = as[r * AW + pb + 4 + t];
                afr[mt][3] = as[(r + 8) * AW + pb + 4 + t];
            }
            unsigned bfr[8][2];
#pragma unroll
            for (int nt = 0; nt < 8; nt++) {
                int n = wn + nt * 8 + g;
                bfr[nt][0] = bs[n * AW + pb + t];
                bfr[nt][1] = bs[n * AW + pb + 4 + t];
            }
#pragma unroll
            for (int mt = 0; mt < 2; mt++)
#pragma unroll
                for (int nt = 0; nt < 8; nt++)
                    mma_f16(acc[mt][nt], afr[mt], bfr[nt]);
        }
        __syncthreads();
        stage ^= 1;
    }

    float* C = args.C[z];
    const float* rowscale = args.rs[z];
    const float* bias = args.b[z];
#pragma unroll
    for (int mt = 0; mt < 2; mt++) {
        int r0 = bm + wm + mt * 16 + g;
        int r1 = r0 + 8;
        float s0 = 1.0f, s1 = 1.0f;
        if (rowscale) {
            if (r0 < M) s0 = rowscale[r0];
            if (r1 < M) s1 = rowscale[r1];
        }
#pragma unroll
        for (int nt = 0; nt < 8; nt++) {
            int c = bn + wn + nt * 8 + t * 2;
            float b0 = 0.0f, b1 = 0.0f;
            if (bias) { b0 = bias[c]; b1 = bias[c + 1]; }
            if (r0 < M) {
                float2 v = make_float2(acc[mt][nt][0] * s0 + b0,
                                       acc[mt][nt][1] * s0 + b1);
                *(float2*)(C + (size_t)r0 * 512 + c) = v;
            }
            if (r1 < M) {
                float2 v = make_float2(acc[mt][nt][2] * s1 + b0,
                                       acc[mt][nt][3] * s1 + b1);
                *(float2*)(C + (size_t)r1 * 512 + c) = v;
            }
        }
    }
}

// ---------------- LN core ----------------
__device__ __forceinline__ float4 ln_elu_core4(
    float4 v, const float* __restrict__ gamma, const float* __restrict__ beta) {
    int t = threadIdx.x;
    float sum = v.x + v.y + v.z + v.w;
    sum = block_reduce_sum_128(sum);
    float u = sum * (1.0f / HH);
    float dx = v.x - u, dy = v.y - u, dz = v.z - u, dw = v.w - u;
    float var = dx * dx + dy * dy + dz * dz + dw * dw;
    var = block_reduce_sum_128(var) * (1.0f / HH);
    float inv = rsqrtf(var + 1e-12f);
    float4 ga = ((const float4*)gamma)[t];
    float4 be = ((const float4*)beta)[t];
    float y0 = ga.x * dx * inv + be.x;
    float y1 = ga.y * dy * inv + be.y;
    float y2 = ga.z * dz * inv + be.z;
    float y3 = ga.w * dw * inv + be.w;
    y0 = (y0 > 0.0f) ? y0 : (expf(y0) - 1.0f);
    y1 = (y1 > 0.0f) ? y1 : (expf(y1) - 1.0f);
    y2 = (y2 > 0.0f) ? y2 : (expf(y2) - 1.0f);
    y3 = (y3 > 0.0f) ? y3 : (expf(y3) - 1.0f);
    return make_float4(y0, y1, y2, y3);
}

// ---------------- mega-fused per-node branch kernel (batched over r) ----------
__global__ __launch_bounds__(128) void fused_branches(
    const int* __restrict__ eid_all, const int* __restrict__ off_all,
    const int* __restrict__ src_all, const float* __restrict__ go,
    const float* __restrict__ el_all, const float* __restrict__ er_all,
    const float* __restrict__ rdi_all,
    const float* __restrict__ bc_l, const float* __restrict__ gc_l,
    const float* __restrict__ bec_l,
    const float* __restrict__ bg_l, const float* __restrict__ gg_l,
    const float* __restrict__ beg_l,
    const float* __restrict__ bs_l, const float* __restrict__ gs_l,
    const float* __restrict__ bes_l,
    __half* __restrict__ out16) {
    const int n = blockIdx.x;
    const int r = blockIdx.y;
    const int* eid = eid_all + (size_t)r * EE;
    const int* off = off_all + (size_t)r * (NN + 1);
    const int* src = src_all + (size_t)r * EE;
    const float* Xc = go + (size_t)(r * 3 + 0) * NNHH;
    const float* f = go + (size_t)(r * 3 + 1) * NNHH;
    const float* Xs = go + (size_t)(r * 3 + 2) * NNHH;
    const float* el = el_all + (size_t)r * NN * NHEADS;
    const float* er = er_all + (size_t)r * NN * NHEADS;
    const float* rdi = rdi_all + (size_t)r * NN;
    const float* bc = bc_l + r * HH;
    const float* gc = gc_l + r * HH;
    const float* bec = bec_l + r * HH;
    const float* bg = bg_l + r * HH;
    const float* gg = gg_l + r * HH;
    const float* beg = beg_l + r * HH;
    const float* bs_ = bs_l + r * HH;
    const float* gs = gs_l + r * HH;
    const float* bes = bes_l + r * HH;

    int p0 = off[n], p1 = off[n + 1];
    int t = threadIdx.x;
    int h = t >> 4;

    __shared__ float sh_m[NHEADS], sh_invs[NHEADS];
    if (t < NHEADS) {
        float ern = er[n * NHEADS + t];
        float mx = -INFINITY;
        for (int p = p0; p < p1; p++) {
            float x = el[src[eid[p]] * NHEADS + t] + ern;
            x = (x > 0.0f) ? x : 0.2f * x;
            mx = fmaxf(mx, x);
        }
        float s = 0.0f;
        for (int p = p0; p < p1; p++) {
            float x = el[src[eid[p]] * NHEADS + t] + ern;
            x = (x > 0.0f) ? x : 0.2f * x;
            s += expf(x - mx);
        }
        sh_m[t] = mx;
        sh_invs[t] = (s > 0.0f) ? (1.0f / s) : 1.0f;
    }
    __syncthreads();

    float mh = sh_m[h];
    float invs = sh_invs[h];
    float ern = er[n * NHEADS + h];

    float4 ac = make_float4(0.f, 0.f, 0.f, 0.f);
    float4 ag = make_float4(0.f, 0.f, 0.f, 0.f);
    for (int p = p0; p < p1; p++) {
        int e = eid[p];
        int sn = src[e];
        float4 rc = ((const float4*)(Xc + (size_t)sn * HH))[t];
        float4 rg = ((const float4*)(f + (size_t)sn * HH))[t];
        float x = el[sn * NHEADS + h] + ern;
        x = (x > 0.0f) ? x : 0.2f * x;
        float a = expf(x - mh) * invs;
        ac.x += rc.x; ac.y += rc.y; ac.z += rc.z; ac.w += rc.w;
        ag.x += a * rg.x; ag.y += a * rg.y; ag.z += a * rg.z; ag.w += a * rg.w;
    }

    float sc = rdi[n];
    float4 bb = ((const float4*)bc)[t];
    float4 v = make_float4(ac.x * sc + bb.x, ac.y * sc + bb.y,
                           ac.z * sc + bb.z, ac.w * sc + bb.w);
    float4 y = ln_elu_core4(v, gc, bec);
    float rx = y.x, ry = y.y, rz = y.z, rw = y.w;

    bb = ((const float4*)bg)[t];
    v = make_float4(ag.x + bb.x, ag.y + bb.y, ag.z + bb.z, ag.w + bb.w);
    y = ln_elu_core4(v, gg, beg);
    rx += y.x; ry += y.y; rz += y.z; rw += y.w;

    float4 xs = ((const float4*)(Xs + (size_t)n * HH))[t];
    bb = ((const float4*)bs_)[t];
    v = make_float4(xs.x + bb.x, xs.y + bb.y, xs.z + bb.z, xs.w + bb.w);
    y = ln_elu_core4(v, gs, bes);
    rx += y.x; ry += y.y; rz += y.z; rw += y.w;

    __half2* op = (__half2*)(out16 + (size_t)n * (RR * HH) + (size_t)r * HH + 4 * t);
    op[0] = __floats2half2_rn(rx, ry);
    op[1] = __floats2half2_rn(rz, rw);
}

// ---------------- GAT attn-score precompute (batched over r) ----------------
__global__ void gat_el_er(const float* __restrict__ go,
                          const float* __restrict__ al_l,
                          const float* __restrict__ ar_l,
                          float* __restrict__ el_all, float* __restrict__ er_all) {
    int idx = blockIdx.x * blockDim.x + threadIdx.x;
    if (idx >= NN * NHEADS) return;
    int r = blockIdx.y;
    int n = idx >> 3;
    int hh = idx & 7;
    const float* f = go + (size_t)(r * 3 + 1) * NNHH;
    const float* fr = f + (size_t)n * HH + hh * DHH;
    const float* a1 = al_l + r * NHEADS * DHH + hh * DHH;
    const float* a2 = ar_l + r * NHEADS * DHH + hh * DHH;
    float s1 = 0.0f, s2 = 0.0f;
#pragma unroll 8
    for (int d = 0; d < DHH; d++) {
        float fv = fr[d];
        s1 += fv * a1[d];
        s2 += fv * a2[d];
    }
    el_all[(size_t)r * NN * NHEADS + idx] = s1;
    er_all[(size_t)r * NN * NHEADS + idx] = s2;
}

// ---------------- relation MHA (3 tokens) + mean ----------------
__global__ __launch_bounds__(256) void mha_mean(
    const float* __restrict__ q, const float* __restrict__ k,
    const float* __restrict__ v, float* __restrict__ out,
    __half* __restrict__ out16) {
    int n = blockIdx.x;
    int hd = threadIdx.x >> 5;
    int lane = threadIdx.x & 31;
    size_t base = (size_t)n * RR * HH + hd * DHH;
    float qa[RR], qb[RR], ka[RR], kb[RR], va[RR], vb[RR];
#pragma unroll
    for (int r = 0; r < RR; r++) {
        size_t off = base + (size_t)r * HH;
        qa[r] = q[off + lane];
        qb[r] = q[off + lane + 32];
        ka[r] = k[off + lane];
        kb[r] = k[off + lane + 32];
        va[r] = v[off + lane];
        vb[r] = v[off + lane + 32];
    }
    float sc[RR][RR];
#pragma unroll
    for (int r = 0; r < RR; r++)
#pragma unroll
        for (int t = 0; t < RR; t++) {
            float p = qa[r] * ka[t] + qb[r] * kb[t];
#pragma unroll
            for (int o = 16; o > 0; o >>= 1) p += __shfl_xor_sync(0xffffffffu, p, o);
            sc[r][t] = p * 0.125f;
        }
    float w0 = 0.0f, w1 = 0.0f, w2 = 0.0f;
#pragma unroll
    for (int r = 0; r < RR; r++) {
        float mx = fmaxf(sc[r][0], fmaxf(sc[r][1], sc[r][2]));
        float e0 = expf(sc[r][0] - mx);
        float e1 = expf(sc[r][1] - mx);
        float e2 = expf(sc[r][2] - mx);
        float inv = 1.0f / (e0 + e1 + e2);
        w0 += e0 * inv;
        w1 += e1 * inv;
        w2 += e2 * inv;
    }
    const float third = 1.0f / 3.0f;
    float oa = (w0 * va[0] + w1 * va[1] + w2 * va[2]) * third;
    float ob = (w0 * vb[0] + w1 * vb[1] + w2 * vb[2]) * third;
    size_t o0 = (size_t)n * HH + hd * DHH + lane;
    out[o0] = oa;
    out[o0 + 32] = ob;
    out16[o0] = __float2half_rn(oa);
    out16[o0 + 32] = __float2half_rn(ob);
}

// ---------------- classifier ----------------
__global__ void classify(const float* __restrict__ h, const float* __restrict__ W,
                         const float* __restrict__ b, float* __restrict__ out) {
    int idx = blockIdx.x * blockDim.x + threadIdx.x;
    if (idx >= NN * NCLSS) return;
    int n = idx / NCLSS;
    int c = idx % NCLSS;
    const float* hr = h + (size_t)n * HH;
    float sum = b[c];
#pragma unroll 8
    for (int j = 0; j < HH; j++) sum += hr[j] * W[j * NCLSS + c];
    out[idx] = sum;
}

// ---------------- launch ----------------
extern "C" void kernel_launch(void* const* d_in, const int* in_sizes, int n_in,
                              void* d_out, int out_size) {
    const float* feature = (const float*)d_in[0];
    const int* src = (const int*)d_in[1];
    const int* dst = (const int*)d_in[2];
    const float* Wc = (const float*)d_in[3];
    const float* bc = (const float*)d_in[4];
    const float* gc = (const float*)d_in[5];
    const float* betac = (const float*)d_in[6];
    const float* Wg = (const float*)d_in[7];
    const float* bg = (const float*)d_in[8];
    const float* al = (const float*)d_in[9];
    const float* ar = (const float*)d_in[10];
    const float* gg = (const float*)d_in[11];
    const float* betag = (const float*)d_in[12];
    const float* Ws = (const float*)d_in[13];
    const float* bs = (const float*)d_in[14];
    const float* gs = (const float*)d_in[15];
    const float* betas = (const float*)d_in[16];
    const float* Wq = (const float*)d_in[17];
    const float* bq = (const float*)d_in[18];
    const float* Wk = (const float*)d_in[19];
    const float* bk = (const float*)d_in[20];
    const float* Wv = (const float*)d_in[21];
    const float* bv = (const float*)d_in[22];
    const float* Wout = (const float*)d_in[23];
    const float* bout = (const float*)d_in[24];
    float* out = (float*)d_out;

    float *p_h, *p_go, *p_q, *p_k, *p_v;
    float *p_rdo, *p_rdi, *p_el, *p_er;
    __half *p_h16, *p_stk16, *p_w16;
    int *p_cnt, *p_cur, *p_off, *p_eid;
    cudaGetSymbolAddress((void**)&p_h, g_h);
    cudaGetSymbolAddress((void**)&p_h16, g_h16);
    cudaGetSymbolAddress((void**)&p_go, g_go);
    cudaGetSymbolAddress((void**)&p_stk16, g_stk16);
    cudaGetSymbolAddress((void**)&p_q, g_q);
    cudaGetSymbolAddress((void**)&p_k, g_k);
    cudaGetSymbolAddress((void**)&p_v, g_v);
    cudaGetSymbolAddress((void**)&p_w16, g_w16);
    cudaGetSymbolAddress((void**)&p_rdo, g_rdo);
    cudaGetSymbolAddress((void**)&p_rdi, g_rdi);
    cudaGetSymbolAddress((void**)&p_el, g_el);
    cudaGetSymbolAddress((void**)&p_er, g_er);
    cudaGetSymbolAddress((void**)&p_cnt, g_cnt);
    cudaGetSymbolAddress((void**)&p_cur, g_cur);
    cudaGetSymbolAddress((void**)&p_off, g_off);
    cudaGetSymbolAddress((void**)&p_eid, g_eid);

    cudaFuncSetAttribute(f16gemm9, cudaFuncAttributeMaxDynamicSharedMemorySize,
                         GEMM_SMEM);

    const size_t WHH = (size_t)HH * HH;
    __half* w16_Wc = p_w16;
    __half* w16_Wg = p_w16 + 6 * WHH;
    __half* w16_Ws = p_w16 + 12 * WHH;
    __half* w16_Wq = p_w16 + 18 * WHH;
    __half* w16_Wk = p_w16 + 20 * WHH;
    __half* w16_Wv = p_w16 + 22 * WHH;

    // transpose+convert weights to [N,K] f16; convert feature to f16
    {
        dim3 tb(32, 8);
        transpose_cvt16<<<dim3(16, 16, 6), tb>>>(Wc, w16_Wc);
        transpose_cvt16<<<dim3(16, 16, 6), tb>>>(Wg, w16_Wg);
        transpose_cvt16<<<dim3(16, 16, 6), tb>>>(Ws, w16_Ws);
        transpose_cvt16<<<dim3(16, 16, 2), tb>>>(Wq, w16_Wq);
        transpose_cvt16<<<dim3(16, 16, 2), tb>>>(Wk, w16_Wk);
        transpose_cvt16<<<dim3(16, 16, 2), tb>>>(Wv, w16_Wv);
        int n4f = (int)(NNHH / 4);
        cvt_f16_vec<<<(n4f + 255) / 256, 256>>>((const float4*)feature,
                                                (__half2*)p_h16, n4f);
    }

    cudaMemsetAsync(p_rdo, 0, (size_t)RR * NN * sizeof(float), 0);
    cudaMemsetAsync(p_rdi, 0, (size_t)RR * NN * sizeof(float), 0);
    cudaMemsetAsync(p_cnt, 0, (size_t)RR * NN * sizeof(int), 0);
    cudaMemsetAsync(p_cur, 0, (size_t)RR * NN * sizeof(int), 0);
    degree_count<<<(RR * EE + 255) / 256, 256>>>(src, dst, p_rdo, p_rdi, p_cnt);
    degree_finalize<<<(RR * NN + 255) / 256, 256>>>(p_rdo, RR * NN);
    degree_finalize<<<(RR * NN + 255) / 256, 256>>>(p_rdi, RR * NN);
    scan_offsets<<<RR, 1024>>>(p_cnt, p_off);
    build_adj<<<(RR * EE + 255) / 256, 256>>>(dst, p_off, p_cur, p_eid);

    const dim3 gemm_grid_n(4, (NN + 127) / 128, 9);
    const dim3 gemm_grid_nr(4, (NN * RR + 127) / 128, 3);
    const dim3 elgrid((NN * NHEADS + 255) / 256, 3);
    const dim3 fgrid(NN, 3);

    for (int l = 0; l < LL; l++) {
        const size_t lbase = (size_t)l * RR;

        G9 a9;
        for (int r = 0; r < RR; r++) {
            const size_t lr = lbase + r;
            a9.W[r * 3 + 0] = w16_Wc + lr * WHH;
            a9.W[r * 3 + 1] = w16_Wg + lr * WHH;
            a9.W[r * 3 + 2] = w16_Ws + lr * WHH;
            for (int bI = 0; bI < 3; bI++) {
                a9.C[r * 3 + bI] = p_go + (size_t)(r * 3 + bI) * NNHH;
                a9.b[r * 3 + bI] = nullptr;
            }
            a9.rs[r * 3 + 0] = p_rdo + (size_t)r * NN;
            a9.rs[r * 3 + 1] = nullptr;
            a9.rs[r * 3 + 2] = nullptr;
        }
        f16gemm9<<<gemm_grid_n, 256, GEMM_SMEM>>>(p_h16, a9, NN);

        gat_el_er<<<elgrid, 256>>>(p_go, al + lbase * NHEADS * DHH,
                                   ar + lbase * NHEADS * DHH, p_el, p_er);
        fused_branches<<<fgrid, 128>>>(
            p_eid, p_off, src, p_go, p_el, p_er, p_rdi,
            bc + lbase * HH, gc + lbase * HH, betac + lbase * HH,
            bg + lbase * HH, gg + lbase * HH, betag + lbase * HH,
            bs + lbase * HH, gs + lbase * HH, betas + lbase * HH,
            p_stk16);

        G9 aq;
        aq.W[0] = w16_Wq + (size_t)l * WHH;
        aq.W[1] = w16_Wk + (size_t)l * WHH;
        aq.W[2] = w16_Wv + (size_t)l * WHH;
        aq.C[0] = p_q;
        aq.C[1] = p_k;
        aq.C[2] = p_v;
        aq.rs[0] = nullptr; aq.rs[1] = nullptr; aq.rs[2] = nullptr;
        aq.b[0] = bq + (size_t)l * HH;
        aq.b[1] = bk + (size_t)l * HH;
        aq.b[2] = bv + (size_t)l * HH;
        for (int zz = 3; zz < 9; zz++) {
            aq.W[zz] = nullptr; aq.C[zz] = nullptr;
            aq.rs[zz] = nullptr; aq.b[zz] = nullptr;
        }
        f16gemm9<<<gemm_grid_nr, 256, GEMM_SMEM>>>(p_stk16, aq, NN * RR);

        mha_mean<<<NN, 256>>>(p_q, p_k, p_v, p_h, p_h16);
    }

    classify<<<(NN * NCLSS + 255) / 256, 256>>>(p_h, Wout, bout, out);
}

// round 14
// speedup vs baseline: 1.5061x; 1.0403x over previous
#include <cuda_runtime.h>
#include <cuda_fp16.h>
#include <math.h>
#include <stdint.h>

#define NN 50000
#define EE 150000
#define RR 3
#define LL 2
#define HH 512
#define NHEADS 8
#define DHH 64
#define NCLSS 23
#define NNHH ((size_t)NN * HH)

// ---------------- scratch (device globals; no allocs allowed) ----------------
__device__ float g_h[NNHH];
__device__ __half g_h16[NNHH];
__device__ float g_go[(size_t)9 * NNHH];
__device__ __half g_stk16[(size_t)NN * RR * HH];
__device__ float g_q[(size_t)NN * RR * HH];
__device__ float g_k[(size_t)NN * RR * HH];
__device__ float g_v[(size_t)NN * RR * HH];
__device__ __half g_w16[(size_t)24 * HH * HH];  // TRANSPOSED [N][K] f16 weights
__device__ float g_rdo[(size_t)RR * NN];
__device__ float g_rdi[(size_t)RR * NN];
__device__ float g_el[(size_t)RR * NN * NHEADS];
__device__ float g_er[(size_t)RR * NN * NHEADS];
// CSR (dst-indexed) per relation
__device__ int g_cnt[(size_t)RR * NN];
__device__ int g_cur[(size_t)RR * NN];
__device__ int g_off[(size_t)RR * (NN + 1)];
__device__ int g_eid[(size_t)RR * EE];

// ---------------- helpers ----------------
__device__ __forceinline__ float block_reduce_sum_128(float val) {
    __shared__ float sh[32];
    __syncthreads();
    int lane = threadIdx.x & 31;
    int wid = threadIdx.x >> 5;
#pragma unroll
    for (int o = 16; o > 0; o >>= 1) val += __shfl_xor_sync(0xffffffffu, val, o);
    if (lane == 0) sh[wid] = val;
    __syncthreads();
    if (wid == 0) {
        float v = (lane < (blockDim.x >> 5)) ? sh[lane] : 0.0f;
#pragma unroll
        for (int o = 16; o > 0; o >>= 1) v += __shfl_xor_sync(0xffffffffu, v, o);
        if (lane == 0) sh[0] = v;
    }
    __syncthreads();
    return sh[0];
}

__device__ __forceinline__ void mma_f16(float* d, const unsigned* a, const unsigned* b) {
    asm volatile(
        "mma.sync.aligned.m16n8k16.row.col.f32.f16.f16.f32 "
        "{%0,%1,%2,%3}, {%4,%5,%6,%7}, {%8,%9}, {%0,%1,%2,%3};"
        : "+f"(d[0]), "+f"(d[1]), "+f"(d[2]), "+f"(d[3])
        : "r"(a[0]), "r"(a[1]), "r"(a[2]), "r"(a[3]), "r"(b[0]), "r"(b[1]));
}

__device__ __forceinline__ void ldsm_x4(unsigned addr, unsigned& r0, unsigned& r1,
                                        unsigned& r2, unsigned& r3) {
    asm volatile(
        "ldmatrix.sync.aligned.m8n8.x4.shared.b16 {%0,%1,%2,%3}, [%4];"
        : "=r"(r0), "=r"(r1), "=r"(r2), "=r"(r3)
        : "r"(addr));
}

__device__ __forceinline__ void cp16(void* smem_dst, const void* gmem_src, bool pred) {
    unsigned saddr = (unsigned)__cvta_generic_to_shared(smem_dst);
    int sz = pred ? 16 : 0;
    asm volatile("cp.async.cg.shared.global [%0], [%1], 16, %2;\n"
                 :: "r"(saddr), "l"(gmem_src), "r"(sz));
}
__device__ __forceinline__ void cp_commit() {
    asm volatile("cp.async.commit_group;\n");
}
template <int N>
__device__ __forceinline__ void cp_wait() {
    asm volatile("cp.async.wait_group %0;\n" :: "n"(N));
}

// ---------------- conversion kernels ----------------
__global__ void cvt_f16_vec(const float4* __restrict__ in,
                            __half2* __restrict__ out, int n4) {
    int i = blockIdx.x * blockDim.x + threadIdx.x;
    if (i < n4) {
        float4 v = in[i];
        out[2 * i] = __floats2half2_rn(v.x, v.y);
        out[2 * i + 1] = __floats2half2_rn(v.z, v.w);
    }
}

// transpose W[K,N] -> Wt[N,K] f16; grid (16,16,nmat), block (32,8)
__global__ void transpose_cvt16(const float* __restrict__ in,
                                __half* __restrict__ out) {
    __shared__ float tile[32][33];
    const float* A = in + (size_t)blockIdx.z * HH * HH;
    __half* O = out + (size_t)blockIdx.z * HH * HH;
    int x = blockIdx.x * 32 + threadIdx.x;
    int y0 = blockIdx.y * 32 + threadIdx.y;
#pragma unroll
    for (int i = 0; i < 32; i += 8)
        tile[threadIdx.y + i][threadIdx.x] = A[(size_t)(y0 + i) * HH + x];
    __syncthreads();
    int ox = blockIdx.y * 32 + threadIdx.x;
    int oy0 = blockIdx.x * 32 + threadIdx.y;
#pragma unroll
    for (int i = 0; i < 32; i += 8)
        O[(size_t)(oy0 + i) * HH + ox] =
            __float2half_rn(tile[threadIdx.x][threadIdx.y + i]);
}

// ---------------- degree + CSR build ----------------
__global__ void degree_count(const int* __restrict__ src, const int* __restrict__ dst,
                             float* __restrict__ rdo, float* __restrict__ rdi,
                             int* __restrict__ cnt) {
    int idx = blockIdx.x * blockDim.x + threadIdx.x;
    if (idx >= RR * EE) return;
    int r = idx / EE;
    int d = dst[idx];
    atomicAdd(&rdo[(size_t)r * NN + src[idx]], 1.0f);
    atomicAdd(&rdi[(size_t)r * NN + d], 1.0f);
    atomicAdd(&cnt[(size_t)r * NN + d], 1);
}

__global__ void degree_finalize(float* __restrict__ p, int n) {
    int idx = blockIdx.x * blockDim.x + threadIdx.x;
    if (idx < n) p[idx] = rsqrtf(fmaxf(p[idx], 1.0f));
}

__global__ __launch_bounds__(1024) void scan_offsets(const int* __restrict__ cnt,
                                                     int* __restrict__ off) {
    int r = blockIdx.x;
    const int* c = cnt + (size_t)r * NN;
    int* o = off + (size_t)r * (NN + 1);
    __shared__ int warp_sums[32];
    __shared__ int s_carry;
    if (threadIdx.x == 0) s_carry = 0;
    __syncthreads();
    int lane = threadIdx.x & 31;
    int w = threadIdx.x >> 5;
    for (int base = 0; base < NN; base += 1024) {
        int idx = base + threadIdx.x;
        int val = (idx < NN) ? c[idx] : 0;
        int x = val;
#pragma unroll
        for (int s = 1; s < 32; s <<= 1) {
            int y = __shfl_up_sync(0xffffffffu, x, s);
            if (lane >= s) x += y;
        }
        if (lane == 31) warp_sums[w] = x;
        __syncthreads();
        if (w == 0) {
            int y = warp_sums[lane];
#pragma unroll
            for (int s = 1; s < 32; s <<= 1) {
                int z = __shfl_up_sync(0xffffffffu, y, s);
                if (lane >= s) y += z;
            }
            warp_sums[lane] = y;
        }
        __syncthreads();
        int excl = x - val + ((w > 0) ? warp_sums[w - 1] : 0) + s_carry;
        if (idx < NN) o[idx] = excl;
        int chunk_total = warp_sums[31];
        __syncthreads();
        if (threadIdx.x == 0) s_carry += chunk_total;
        __syncthreads();
    }
    if (threadIdx.x == 0) o[NN] = s_carry;
}

__global__ void build_adj(const int* __restrict__ dst, const int* __restrict__ off,
                          int* __restrict__ cur, int* __restrict__ eid) {
    int idx = blockIdx.x * blockDim.x + threadIdx.x;
    if (idx >= RR * EE) return;
    int r = idx / EE;
    int e = idx - r * EE;
    int d = dst[idx];
    int pos = atomicAdd(&cur[(size_t)r * NN + d], 1);
    eid[(size_t)r * EE + off[(size_t)r * (NN + 1) + d] + pos] = e;
}

// ---------------- batched FP16 tensor-core GEMM (up to 9 weights, shared A) ---
// C_z[M,512] = A[M,512] @ Wt_z[512,512]^T (* rs_z[row]) (+ b_z[col])
// A f16 [M,K]; Wt f16 [N,K]. m16n8k16, ldmatrix fragment loads.
// BK=64, 2-stage cp.async, 73.7KB smem -> 2 CTAs/SM (do NOT deepen: R10).
#define AW 36  // words per 64-half row (32 data + 4 pad) -> LDSM conflict-free
#define AS_WORDS (128 * AW)
#define BS_WORDS (128 * AW)
#define GEMM_SMEM ((2 * AS_WORDS + 2 * BS_WORDS) * 4)

struct G9 {
    const __half* W[9];
    float* C[9];
    const float* rs[9];
    const float* b[9];
};

__global__ __launch_bounds__(256) void f16gemm9(
    const __half* __restrict__ A, G9 args, int M) {
    extern __shared__ unsigned sm[];
    unsigned* As = sm;                 // 2 stages
    unsigned* Bs = sm + 2 * AS_WORDS;  // 2 stages

    const int z = blockIdx.z;
    const __half* Wt = args.W[z];
    const int bm = blockIdx.y * 128;
    const int bn = blockIdx.x * 128;
    const int tid = threadIdx.x;
    const int warp = tid >> 5;
    const int lane = tid & 31;
    const int g = lane >> 2;
    const int t = lane & 3;
    const int wm = (warp >> 1) * 32;
    const int wn = (warp & 1) * 64;

    float acc[2][8][4];
#pragma unroll
    for (int i = 0; i < 2; i++)
#pragma unroll
        for (int j = 0; j < 8; j++)
#pragma unroll
            for (int q = 0; q < 4; q++) acc[i][j][q] = 0.0f;

    int l_row[4], l_c[4];
#pragma unroll
    for (int i = 0; i < 4; i++) {
        int slot = tid + i * 256;
        l_row[i] = slot >> 3;
        l_c[i] = slot & 7;
    }

    // ldmatrix per-lane base addresses (bytes into stage-0 smem)
    const unsigned as_base = (unsigned)__cvta_generic_to_shared(As);
    const unsigned bs_base = (unsigned)__cvta_generic_to_shared(Bs);
    // A x4: lanes0-7 tile(rows,klo) 8-15 (rows+8,klo) 16-23 (rows,khi) 24-31 (rows+8,khi)
    const unsigned a_lane_off =
        ((wm + (lane & 7) + ((lane >> 3) & 1) * 8) * AW + ((lane >> 4) & 1) * 4) * 4;
    // B x4 over nt pair: lanes0-7 (n,klo) 8-15 (n,khi) 16-23 (n+8,klo) 24-31 (n+8,khi)
    const unsigned b_lane_off =
        ((wn + (lane & 7) + ((lane >> 4) & 1) * 8) * AW + ((lane >> 3) & 1) * 4) * 4;

#define LOAD_TILE(k0, st)                                                          \
    do {                                                                           \
        unsigned* as = As + (st)*AS_WORDS;                                         \
        unsigned* bs = Bs + (st)*BS_WORDS;                                         \
        _Pragma("unroll") for (int i = 0; i < 4; i++) {                            \
            int row = l_row[i], c = l_c[i];                                        \
            int gr = bm + row;                                                     \
            cp16(as + row * AW + c * 4,                                            \
                 A + (size_t)gr * 512 + (k0) + c * 8, gr < M);                     \
            cp16(bs + row * AW + c * 4,                                            \
                 Wt + (size_t)(bn + row) * 512 + (k0) + c * 8, true);              \
        }                                                                          \
    } while (0)

    LOAD_TILE(0, 0);
    cp_commit();
    int stage = 0;
#pragma unroll 1
    for (int it = 0; it < 8; it++) {
        if (it + 1 < 8) {
            LOAD_TILE((it + 1) * 64, stage ^ 1);
            cp_commit();
            cp_wait<1>();
        } else {
            cp_wait<0>();
        }
        __syncthreads();
        const unsigned a_st = as_base + a_lane_off + stage * (AS_WORDS * 4);
        const unsigned b_st = bs_base + b_lane_off + stage * (BS_WORDS * 4);
#pragma unroll
        for (int ks = 0; ks < 4; ks++) {
            const unsigned kb = ks * 32;  // 8 words per k-step
            unsigned afr[2][4];
#pragma unroll
            for (int mt = 0; mt < 2; mt++)
                ldsm_x4(a_st + mt * (16 * AW * 4) + kb,
                        afr[mt][0], afr[mt][1], afr[mt][2], afr[mt][3]);
            unsigned bfr[8][2];
#pragma unroll
            for (int ntp = 0; ntp < 4; ntp++)
                ldsm_x4(b_st + ntp * (16 * AW * 4) + kb,
                        bfr[2 * ntp][0], bfr[2 * ntp][1],
                        bfr[2 * ntp + 1][0], bfr[2 * ntp + 1][1]);
#pragma unroll
            for (int mt = 0; mt < 2; mt++)
#pragma unroll
                for (int nt = 0; nt < 8; nt++)
                    mma_f16(acc[mt][nt], afr[mt], bfr[nt]);
        }
        __syncthreads();
        stage ^= 1;
    }

    float* C = args.C[z];
    const float* rowscale = args.rs[z];
    const float* bias = args.b[z];
#pragma unroll
    for (int mt = 0; mt < 2; mt++) {
        int r0 = bm + wm + mt * 16 + g;
        int r1 = r0 + 8;
        float s0 = 1.0f, s1 = 1.0f;
        if (rowscale) {
            if (r0 < M) s0 = rowscale[r0];
            if (r1 < M) s1 = rowscale[r1];
        }
#pragma unroll
        for (int nt = 0; nt < 8; nt++) {
            int c = bn + wn + nt * 8 + t * 2;
            float b0 = 0.0f, b1 = 0.0f;
            if (bias) { b0 = bias[c]; b1 = bias[c + 1]; }
            if (r0 < M) {
                float2 v = make_float2(acc[mt][nt][0] * s0 + b0,
                                       acc[mt][nt][1] * s0 + b1);
                *(float2*)(C + (size_t)r0 * 512 + c) = v;
            }
            if (r1 < M) {
                float2 v = make_float2(acc[mt][nt][2] * s1 + b0,
                                       acc[mt][nt][3] * s1 + b1);
                *(float2*)(C + (size_t)r1 * 512 + c) = v;
            }
        }
    }
}

// ---------------- LN core ----------------
__device__ __forceinline__ float4 ln_elu_core4(
    float4 v, const float* __restrict__ gamma, const float* __restrict__ beta) {
    int t = threadIdx.x;
    float sum = v.x + v.y + v.z + v.w;
    sum = block_reduce_sum_128(sum);
    float u = sum * (1.0f / HH);
    float dx = v.x - u, dy = v.y - u, dz = v.z - u, dw = v.w - u;
    float var = dx * dx + dy * dy + dz * dz + dw * dw;
    var = block_reduce_sum_128(var) * (1.0f / HH);
    float inv = rsqrtf(var + 1e-12f);
    float4 ga = ((const float4*)gamma)[t];
    float4 be = ((const float4*)beta)[t];
    float y0 = ga.x * dx * inv + be.x;
    float y1 = ga.y * dy * inv + be.y;
    float y2 = ga.z * dz * inv + be.z;
    float y3 = ga.w * dw * inv + be.w;
    y0 = (y0 > 0.0f) ? y0 : (expf(y0) - 1.0f);
    y1 = (y1 > 0.0f) ? y1 : (expf(y1) - 1.0f);
    y2 = (y2 > 0.0f) ? y2 : (expf(y2) - 1.0f);
    y3 = (y3 > 0.0f) ? y3 : (expf(y3) - 1.0f);
    return make_float4(y0, y1, y2, y3);
}

// ---------------- mega-fused per-node branch kernel (batched over r) ----------
__global__ __launch_bounds__(128) void fused_branches(
    const int* __restrict__ eid_all, const int* __restrict__ off_all,
    const int* __restrict__ src_all, const float* __restrict__ go,
    const float* __restrict__ el_all, const float* __restrict__ er_all,
    const float* __restrict__ rdi_all,
    const float* __restrict__ bc_l, const float* __restrict__ gc_l,
    const float* __restrict__ bec_l,
    const float* __restrict__ bg_l, const float* __restrict__ gg_l,
    const float* __restrict__ beg_l,
    const float* __restrict__ bs_l, const float* __restrict__ gs_l,
    const float* __restrict__ bes_l,
    __half* __restrict__ out16) {
    const int n = blockIdx.x;
    const int r = blockIdx.y;
    const int* eid = eid_all + (size_t)r * EE;
    const int* off = off_all + (size_t)r * (NN + 1);
    const int* src = src_all + (size_t)r * EE;
    const float* Xc = go + (size_t)(r * 3 + 0) * NNHH;
    const float* f = go + (size_t)(r * 3 + 1) * NNHH;
    const float* Xs = go + (size_t)(r * 3 + 2) * NNHH;
    const float* el = el_all + (size_t)r * NN * NHEADS;
    const float* er = er_all + (size_t)r * NN * NHEADS;
    const float* rdi = rdi_all + (size_t)r * NN;
    const float* bc = bc_l + r * HH;
    const float* gc = gc_l + r * HH;
    const float* bec = bec_l + r * HH;
    const float* bg = bg_l + r * HH;
    const float* gg = gg_l + r * HH;
    const float* beg = beg_l + r * HH;
    const float* bs_ = bs_l + r * HH;
    const float* gs = gs_l + r * HH;
    const float* bes = bes_l + r * HH;

    int p0 = off[n], p1 = off[n + 1];
    int t = threadIdx.x;
    int h = t >> 4;

    __shared__ float sh_m[NHEADS], sh_invs[NHEADS];
    if (t < NHEADS) {
        float ern = er[n * NHEADS + t];
        float mx = -INFINITY;
        for (int p = p0; p < p1; p++) {
            float x = el[src[eid[p]] * NHEADS + t] + ern;
            x = (x > 0.0f) ? x : 0.2f * x;
            mx = fmaxf(mx, x);
        }
        float s = 0.0f;
        for (int p = p0; p < p1; p++) {
            float x = el[src[eid[p]] * NHEADS + t] + ern;
            x = (x > 0.0f) ? x : 0.2f * x;
            s += expf(x - mx);
        }
        sh_m[t] = mx;
        sh_invs[t] = (s > 0.0f) ? (1.0f / s) : 1.0f;
    }
    __syncthreads();

    float mh = sh_m[h];
    float invs = sh_invs[h];
    float ern = er[n * NHEADS + h];

    float4 ac = make_float4(0.f, 0.f, 0.f, 0.f);
    float4 ag = make_float4(0.f, 0.f, 0.f, 0.f);
    for (int p = p0; p < p1; p++) {
        int e = eid[p];
        int sn = src[e];
        float4 rc = ((const float4*)(Xc + (size_t)sn * HH))[t];
        float4 rg = ((const float4*)(f + (size_t)sn * HH))[t];
        float x = el[sn * NHEADS + h] + ern;
        x = (x > 0.0f) ? x : 0.2f * x;
        float a = expf(x - mh) * invs;
        ac.x += rc.x; ac.y += rc.y; ac.z += rc.z; ac.w += rc.w;
        ag.x += a * rg.x; ag.y += a * rg.y; ag.z += a * rg.z; ag.w += a * rg.w;
    }

    float sc = rdi[n];
    float4 bb = ((const float4*)bc)[t];
    float4 v = make_float4(ac.x * sc + bb.x, ac.y * sc + bb.y,
                           ac.z * sc + bb.z, ac.w * sc + bb.w);
    float4 y = ln_elu_core4(v, gc, bec);
    float rx = y.x, ry = y.y, rz = y.z, rw = y.w;

    bb = ((const float4*)bg)[t];
    v = make_float4(ag.x + bb.x, ag.y + bb.y, ag.z + bb.z, ag.w + bb.w);
    y = ln_elu_core4(v, gg, beg);
    rx += y.x; ry += y.y; rz += y.z; rw += y.w;

    float4 xs = ((const float4*)(Xs + (size_t)n * HH))[t];
    bb = ((const float4*)bs_)[t];
    v = make_float4(xs.x + bb.x, xs.y + bb.y, xs.z + bb.z, xs.w + bb.w);
    y = ln_elu_core4(v, gs, bes);
    rx += y.x; ry += y.y; rz += y.z; rw += y.w;

    __half2* op = (__half2*)(out16 + (size_t)n * (RR * HH) + (size_t)r * HH + 4 * t);
    op[0] = __floats2half2_rn(rx, ry);
    op[1] = __floats2half2_rn(rz, rw);
}

// ---------------- GAT attn-score precompute (batched over r) ----------------
__global__ void gat_el_er(const float* __restrict__ go,
                          const float* __restrict__ al_l,
                          const float* __restrict__ ar_l,
                          float* __restrict__ el_all, float* __restrict__ er_all) {
    int idx = blockIdx.x * blockDim.x + threadIdx.x;
    if (idx >= NN * NHEADS) return;
    int r = blockIdx.y;
    int n = idx >> 3;
    int hh = idx & 7;
    const float* f = go + (size_t)(r * 3 + 1) * NNHH;
    const float* fr = f + (size_t)n * HH + hh * DHH;
    const float* a1 = al_l + r * NHEADS * DHH + hh * DHH;
    const float* a2 = ar_l + r * NHEADS * DHH + hh * DHH;
    float s1 = 0.0f, s2 = 0.0f;
#pragma unroll 8
    for (int d = 0; d < DHH; d++) {
        float fv = fr[d];
        s1 += fv * a1[d];
        s2 += fv * a2[d];
    }
    el_all[(size_t)r * NN * NHEADS + idx] = s1;
    er_all[(size_t)r * NN * NHEADS + idx] = s2;
}

// ---------------- relation MHA (3 tokens) + mean ----------------
__global__ __launch_bounds__(256) void mha_mean(
    const float* __restrict__ q, const float* __restrict__ k,
    const float* __restrict__ v, float* __restrict__ out,
    __half* __restrict__ out16) {
    int n = blockIdx.x;
    int hd = threadIdx.x >> 5;
    int lane = threadIdx.x & 31;
    size_t base = (size_t)n * RR * HH + hd * DHH;
    float qa[RR], qb[RR], ka[RR], kb[RR], va[RR], vb[RR];
#pragma unroll
    for (int r = 0; r < RR; r++) {
        size_t off = base + (size_t)r * HH;
        qa[r] = q[off + lane];
        qb[r] = q[off + lane + 32];
        ka[r] = k[off + lane];
        kb[r] = k[off + lane + 32];
        va[r] = v[off + lane];
        vb[r] = v[off + lane + 32];
    }
    float sc[RR][RR];
#pragma unroll
    for (int r = 0; r < RR; r++)
#pragma unroll
        for (int t = 0; t < RR; t++) {
            float p = qa[r] * ka[t] + qb[r] * kb[t];
#pragma unroll
            for (int o = 16; o > 0; o >>= 1) p += __shfl_xor_sync(0xffffffffu, p, o);
            sc[r][t] = p * 0.125f;
        }
    float w0 = 0.0f, w1 = 0.0f, w2 = 0.0f;
#pragma unroll
    for (int r = 0; r < RR; r++) {
        float mx = fmaxf(sc[r][0], fmaxf(sc[r][1], sc[r][2]));
        float e0 = expf(sc[r][0] - mx);
        float e1 = expf(sc[r][1] - mx);
        float e2 = expf(sc[r][2] - mx);
        float inv = 1.0f / (e0 + e1 + e2);
        w0 += e0 * inv;
        w1 += e1 * inv;
        w2 += e2 * inv;
    }
    const float third = 1.0f / 3.0f;
    float oa = (w0 * va[0] + w1 * va[1] + w2 * va[2]) * third;
    float ob = (w0 * vb[0] + w1 * vb[1] + w2 * vb[2]) * third;
    size_t o0 = (size_t)n * HH + hd * DHH + lane;
    out[o0] = oa;
    out[o0 + 32] = ob;
    out16[o0] = __float2half_rn(oa);
    out16[o0 + 32] = __float2half_rn(ob);
}

// ---------------- classifier ----------------
__global__ void classify(const float* __restrict__ h, const float* __restrict__ W,
                         const float* __restrict__ b, float* __restrict__ out) {
    int idx = blockIdx.x * blockDim.x + threadIdx.x;
    if (idx >= NN * NCLSS) return;
    int n = idx / NCLSS;
    int c = idx % NCLSS;
    const float* hr = h + (size_t)n * HH;
    float sum = b[c];
#pragma unroll 8
    for (int j = 0; j < HH; j++) sum += hr[j] * W[j * NCLSS + c];
    out[idx] = sum;
}

// ---------------- launch ----------------
extern "C" void kernel_launch(void* const* d_in, const int* in_sizes, int n_in,
                              void* d_out, int out_size) {
    const float* feature = (const float*)d_in[0];
    const int* src = (const int*)d_in[1];
    const int* dst = (const int*)d_in[2];
    const float* Wc = (const float*)d_in[3];
    const float* bc = (const float*)d_in[4];
    const float* gc = (const float*)d_in[5];
    const float* betac = (const float*)d_in[6];
    const float* Wg = (const float*)d_in[7];
    const float* bg = (const float*)d_in[8];
    const float* al = (const float*)d_in[9];
    const float* ar = (const float*)d_in[10];
    const float* gg = (const float*)d_in[11];
    const float* betag = (const float*)d_in[12];
    const float* Ws = (const float*)d_in[13];
    const float* bs = (const float*)d_in[14];
    const float* gs = (const float*)d_in[15];
    const float* betas = (const float*)d_in[16];
    const float* Wq = (const float*)d_in[17];
    const float* bq = (const float*)d_in[18];
    const float* Wk = (const float*)d_in[19];
    const float* bk = (const float*)d_in[20];
    const float* Wv = (const float*)d_in[21];
    const float* bv = (const float*)d_in[22];
    const float* Wout = (const float*)d_in[23];
    const float* bout = (const float*)d_in[24];
    float* out = (float*)d_out;

    float *p_h, *p_go, *p_q, *p_k, *p_v;
    float *p_rdo, *p_rdi, *p_el, *p_er;
    __half *p_h16, *p_stk16, *p_w16;
    int *p_cnt, *p_cur, *p_off, *p_eid;
    cudaGetSymbolAddress((void**)&p_h, g_h);
    cudaGetSymbolAddress((void**)&p_h16, g_h16);
    cudaGetSymbolAddress((void**)&p_go, g_go);
    cudaGetSymbolAddress((void**)&p_stk16, g_stk16);
    cudaGetSymbolAddress((void**)&p_q, g_q);
    cudaGetSymbolAddress((void**)&p_k, g_k);
    cudaGetSymbolAddress((void**)&p_v, g_v);
    cudaGetSymbolAddress((void**)&p_w16, g_w16);
    cudaGetSymbolAddress((void**)&p_rdo, g_rdo);
    cudaGetSymbolAddress((void**)&p_rdi, g_rdi);
    cudaGetSymbolAddress((void**)&p_el, g_el);
    cudaGetSymbolAddress((void**)&p_er, g_er);
    cudaGetSymbolAddress((void**)&p_cnt, g_cnt);
    cudaGetSymbolAddress((void**)&p_cur, g_cur);
    cudaGetSymbolAddress((void**)&p_off, g_off);
    cudaGetSymbolAddress((void**)&p_eid, g_eid);

    cudaFuncSetAttribute(f16gemm9, cudaFuncAttributeMaxDynamicSharedMemorySize,
                         GEMM_SMEM);

    const size_t WHH = (size_t)HH * HH;
    __half* w16_Wc = p_w16;
    __half* w16_Wg = p_w16 + 6 * WHH;
    __half* w16_Ws = p_w16 + 12 * WHH;
    __half* w16_Wq = p_w16 + 18 * WHH;
    __half* w16_Wk = p_w16 + 20 * WHH;
    __half* w16_Wv = p_w16 + 22 * WHH;

    {
        dim3 tb(32, 8);
        transpose_cvt16<<<dim3(16, 16, 6), tb>>>(Wc, w16_Wc);
        transpose_cvt16<<<dim3(16, 16, 6), tb>>>(Wg, w16_Wg);
        transpose_cvt16<<<dim3(16, 16, 6), tb>>>(Ws, w16_Ws);
        transpose_cvt16<<<dim3(16, 16, 2), tb>>>(Wq, w16_Wq);
        transpose_cvt16<<<dim3(16, 16, 2), tb>>>(Wk, w16_Wk);
        transpose_cvt16<<<dim3(16, 16, 2), tb>>>(Wv, w16_Wv);
        int n4f = (int)(NNHH / 4);
        cvt_f16_vec<<<(n4f + 255) / 256, 256>>>((const float4*)feature,
                                                (__half2*)p_h16, n4f);
    }

    cudaMemsetAsync(p_rdo, 0, (size_t)RR * NN * sizeof(float), 0);
    cudaMemsetAsync(p_rdi, 0, (size_t)RR * NN * sizeof(float), 0);
    cudaMemsetAsync(p_cnt, 0, (size_t)RR * NN * sizeof(int), 0);
    cudaMemsetAsync(p_cur, 0, (size_t)RR * NN * sizeof(int), 0);
    degree_count<<<(RR * EE + 255) / 256, 256>>>(src, dst, p_rdo, p_rdi, p_cnt);
    degree_finalize<<<(RR * NN + 255) / 256, 256>>>(p_rdo, RR * NN);
    degree_finalize<<<(RR * NN + 255) / 256, 256>>>(p_rdi, RR * NN);
    scan_offsets<<<RR, 1024>>>(p_cnt, p_off);
    build_adj<<<(RR * EE + 255) / 256, 256>>>(dst, p_off, p_cur, p_eid);

    const dim3 gemm_grid_n(4, (NN + 127) / 128, 9);
    const dim3 gemm_grid_nr(4, (NN * RR + 127) / 128, 3);
    const dim3 elgrid((NN * NHEADS + 255) / 256, 3);
    const dim3 fgrid(NN, 3);

    for (int l = 0; l < LL; l++) {
        const size_t lbase = (size_t)l * RR;

        G9 a9;
        for (int r = 0; r < RR; r++) {
            const size_t lr = lbase + r;
            a9.W[r * 3 + 0] = w16_Wc + lr * WHH;
            a9.W[r * 3 + 1] = w16_Wg + lr * WHH;
            a9.W[r * 3 + 2] = w16_Ws + lr * WHH;
            for (int bI = 0; bI < 3; bI++) {
                a9.C[r * 3 + bI] = p_go + (size_t)(r * 3 + bI) * NNHH;
                a9.b[r * 3 + bI] = nullptr;
            }
            a9.rs[r * 3 + 0] = p_rdo + (size_t)r * NN;
            a9.rs[r * 3 + 1] = nullptr;
            a9.rs[r * 3 + 2] = nullptr;
        }
        f16gemm9<<<gemm_grid_n, 256, GEMM_SMEM>>>(p_h16, a9, NN);

        gat_el_er<<<elgrid, 256>>>(p_go, al + lbase * NHEADS * DHH,
                                   ar + lbase * NHEADS * DHH, p_el, p_er);
        fused_branches<<<fgrid, 128>>>(
            p_eid, p_off, src, p_go, p_el, p_er, p_rdi,
            bc + lbase * HH, gc + lbase * HH, betac + lbase * HH,
            bg + lbase * HH, gg + lbase * HH, betag + lbase * HH,
            bs + lbase * HH, gs + lbase * HH, betas + lbase * HH,
            p_stk16);

        G9 aq;
        aq.W[0] = w16_Wq + (size_t)l * WHH;
        aq.W[1] = w16_Wk + (size_t)l * WHH;
        aq.W[2] = w16_Wv + (size_t)l * WHH;
        aq.C[0] = p_q;
        aq.C[1] = p_k;
        aq.C[2] = p_v;
        aq.rs[0] = nullptr; aq.rs[1] = nullptr; aq.rs[2] = nullptr;
        aq.b[0] = bq + (size_t)l * HH;
        aq.b[1] = bk + (size_t)l * HH;
        aq.b[2] = bv + (size_t)l * HH;
        for (int zz = 3; zz < 9; zz++) {
            aq.W[zz] = nullptr; aq.C[zz] = nullptr;
            aq.rs[zz] = nullptr; aq.b[zz] = nullptr;
        }
        f16gemm9<<<gemm_grid_nr, 256, GEMM_SMEM>>>(p_stk16, aq, NN * RR);

        mha_mean<<<NN, 256>>>(p_q, p_k, p_v, p_h, p_h16);
    }

    classify<<<(NN * NCLSS + 255) / 256, 256>>>(p_h, Wout, bout, out);
}

// round 15
// speedup vs baseline: 1.5344x; 1.0188x over previous
#include <cuda_runtime.h>
#include <cuda_fp16.h>
#include <math.h>
#include <stdint.h>

#define NN 50000
#define EE 150000
#define RR 3
#define LL 2
#define HH 512
#define NHEADS 8
#define DHH 64
#define NCLSS 23
#define NNHH ((size_t)NN * HH)

// ---------------- scratch (device globals; no allocs allowed) ----------------
__device__ float g_h[NNHH];
__device__ __half g_h16[NNHH];
__device__ __half g_go16[(size_t)9 * NNHH];  // GEMM outputs (f16)
__device__ __half g_stk16[(size_t)NN * RR * HH];
__device__ __half g_q[(size_t)NN * RR * HH];
__device__ __half g_k[(size_t)NN * RR * HH];
__device__ __half g_v[(size_t)NN * RR * HH];
__device__ __half g_w16[(size_t)24 * HH * HH];  // TRANSPOSED [N][K] f16 weights
__device__ float g_rdo[(size_t)RR * NN];
__device__ float g_rdi[(size_t)RR * NN];
__device__ float g_el[(size_t)RR * NN * NHEADS];
__device__ float g_er[(size_t)RR * NN * NHEADS];
// CSR (dst-indexed) per relation
__device__ int g_cnt[(size_t)RR * NN];
__device__ int g_cur[(size_t)RR * NN];
__device__ int g_off[(size_t)RR * (NN + 1)];
__device__ int g_eid[(size_t)RR * EE];

// ---------------- helpers ----------------
__device__ __forceinline__ float block_reduce_sum_128(float val) {
    __shared__ float sh[32];
    __syncthreads();
    int lane = threadIdx.x & 31;
    int wid = threadIdx.x >> 5;
#pragma unroll
    for (int o = 16; o > 0; o >>= 1) val += __shfl_xor_sync(0xffffffffu, val, o);
    if (lane == 0) sh[wid] = val;
    __syncthreads();
    if (wid == 0) {
        float v = (lane < (blockDim.x >> 5)) ? sh[lane] : 0.0f;
#pragma unroll
        for (int o = 16; o > 0; o >>= 1) v += __shfl_xor_sync(0xffffffffu, v, o);
        if (lane == 0) sh[0] = v;
    }
    __syncthreads();
    return sh[0];
}

__device__ __forceinline__ void mma_f16(float* d, const unsigned* a, const unsigned* b) {
    asm volatile(
        "mma.sync.aligned.m16n8k16.row.col.f32.f16.f16.f32 "
        "{%0,%1,%2,%3}, {%4,%5,%6,%7}, {%8,%9}, {%0,%1,%2,%3};"
        : "+f"(d[0]), "+f"(d[1]), "+f"(d[2]), "+f"(d[3])
        : "r"(a[0]), "r"(a[1]), "r"(a[2]), "r"(a[3]), "r"(b[0]), "r"(b[1]));
}

__device__ __forceinline__ void ldsm_x4(unsigned addr, unsigned& r0, unsigned& r1,
                                        unsigned& r2, unsigned& r3) {
    asm volatile(
        "ldmatrix.sync.aligned.m8n8.x4.shared.b16 {%0,%1,%2,%3}, [%4];"
        : "=r"(r0), "=r"(r1), "=r"(r2), "=r"(r3)
        : "r"(addr));
}

__device__ __forceinline__ void cp16(void* smem_dst, const void* gmem_src, bool pred) {
    unsigned saddr = (unsigned)__cvta_generic_to_shared(smem_dst);
    int sz = pred ? 16 : 0;
    asm volatile("cp.async.cg.shared.global [%0], [%1], 16, %2;\n"
                 :: "r"(saddr), "l"(gmem_src), "r"(sz));
}
__device__ __forceinline__ void cp_commit() {
    asm volatile("cp.async.commit_group;\n");
}
template <int N>
__device__ __forceinline__ void cp_wait() {
    asm volatile("cp.async.wait_group %0;\n" :: "n"(N));
}

// ---------------- conversion kernels ----------------
__global__ void cvt_f16_vec(const float4* __restrict__ in,
                            __half2* __restrict__ out, int n4) {
    int i = blockIdx.x * blockDim.x + threadIdx.x;
    if (i < n4) {
        float4 v = in[i];
        out[2 * i] = __floats2half2_rn(v.x, v.y);
        out[2 * i + 1] = __floats2half2_rn(v.z, v.w);
    }
}

// transpose W[K,N] -> Wt[N,K] f16; grid (16,16,nmat), block (32,8)
__global__ void transpose_cvt16(const float* __restrict__ in,
                                __half* __restrict__ out) {
    __shared__ float tile[32][33];
    const float* A = in + (size_t)blockIdx.z * HH * HH;
    __half* O = out + (size_t)blockIdx.z * HH * HH;
    int x = blockIdx.x * 32 + threadIdx.x;
    int y0 = blockIdx.y * 32 + threadIdx.y;
#pragma unroll
    for (int i = 0; i < 32; i += 8)
        tile[threadIdx.y + i][threadIdx.x] = A[(size_t)(y0 + i) * HH + x];
    __syncthreads();
    int ox = blockIdx.y * 32 + threadIdx.x;
    int oy0 = blockIdx.x * 32 + threadIdx.y;
#pragma unroll
    for (int i = 0; i < 32; i += 8)
        O[(size_t)(oy0 + i) * HH + ox] =
            __float2half_rn(tile[threadIdx.x][threadIdx.y + i]);
}

// ---------------- degree + CSR build ----------------
__global__ void degree_count(const int* __restrict__ src, const int* __restrict__ dst,
                             float* __restrict__ rdo, float* __restrict__ rdi,
                             int* __restrict__ cnt) {
    int idx = blockIdx.x * blockDim.x + threadIdx.x;
    if (idx >= RR * EE) return;
    int r = idx / EE;
    int d = dst[idx];
    atomicAdd(&rdo[(size_t)r * NN + src[idx]], 1.0f);
    atomicAdd(&rdi[(size_t)r * NN + d], 1.0f);
    atomicAdd(&cnt[(size_t)r * NN + d], 1);
}

__global__ void degree_finalize(float* __restrict__ p, int n) {
    int idx = blockIdx.x * blockDim.x + threadIdx.x;
    if (idx < n) p[idx] = rsqrtf(fmaxf(p[idx], 1.0f));
}

__global__ __launch_bounds__(1024) void scan_offsets(const int* __restrict__ cnt,
                                                     int* __restrict__ off) {
    int r = blockIdx.x;
    const int* c = cnt + (size_t)r * NN;
    int* o = off + (size_t)r * (NN + 1);
    __shared__ int warp_sums[32];
    __shared__ int s_carry;
    if (threadIdx.x == 0) s_carry = 0;
    __syncthreads();
    int lane = threadIdx.x & 31;
    int w = threadIdx.x >> 5;
    for (int base = 0; base < NN; base += 1024) {
        int idx = base + threadIdx.x;
        int val = (idx < NN) ? c[idx] : 0;
        int x = val;
#pragma unroll
        for (int s = 1; s < 32; s <<= 1) {
            int y = __shfl_up_sync(0xffffffffu, x, s);
            if (lane >= s) x += y;
        }
        if (lane == 31) warp_sums[w] = x;
        __syncthreads();
        if (w == 0) {
            int y = warp_sums[lane];
#pragma unroll
            for (int s = 1; s < 32; s <<= 1) {
                int z = __shfl_up_sync(0xffffffffu, y, s);
                if (lane >= s) y += z;
            }
            warp_sums[lane] = y;
        }
        __syncthreads();
        int excl = x - val + ((w > 0) ? warp_sums[w - 1] : 0) + s_carry;
        if (idx < NN) o[idx] = excl;
        int chunk_total = warp_sums[31];
        __syncthreads();
        if (threadIdx.x == 0) s_carry += chunk_total;
        __syncthreads();
    }
    if (threadIdx.x == 0) o[NN] = s_carry;
}

__global__ void build_adj(const int* __restrict__ dst, const int* __restrict__ off,
                          int* __restrict__ cur, int* __restrict__ eid) {
    int idx = blockIdx.x * blockDim.x + threadIdx.x;
    if (idx >= RR * EE) return;
    int r = idx / EE;
    int e = idx - r * EE;
    int d = dst[idx];
    int pos = atomicAdd(&cur[(size_t)r * NN + d], 1);
    eid[(size_t)r * EE + off[(size_t)r * (NN + 1) + d] + pos] = e;
}

// ---------------- batched FP16 tensor-core GEMM (up to 9 weights, shared A) ---
// C_z[M,512](f16) = A[M,512] @ Wt_z[512,512]^T (* rs_z[row]) (+ b_z[col])
// BK=64, 2-stage cp.async, ldmatrix loads, 73.7KB smem -> 2 CTAs/SM.
#define AW 36
#define AS_WORDS (128 * AW)
#define BS_WORDS (128 * AW)
#define GEMM_SMEM ((2 * AS_WORDS + 2 * BS_WORDS) * 4)

struct G9 {
    const __half* W[9];
    __half* C[9];
    const float* rs[9];
    const float* b[9];
};

__global__ __launch_bounds__(256) void f16gemm9(
    const __half* __restrict__ A, G9 args, int M) {
    extern __shared__ unsigned sm[];
    unsigned* As = sm;
    unsigned* Bs = sm + 2 * AS_WORDS;

    const int z = blockIdx.z;
    const __half* Wt = args.W[z];
    const int bm = blockIdx.y * 128;
    const int bn = blockIdx.x * 128;
    const int tid = threadIdx.x;
    const int warp = tid >> 5;
    const int lane = tid & 31;
    const int g = lane >> 2;
    const int t = lane & 3;
    const int wm = (warp >> 1) * 32;
    const int wn = (warp & 1) * 64;

    float acc[2][8][4];
#pragma unroll
    for (int i = 0; i < 2; i++)
#pragma unroll
        for (int j = 0; j < 8; j++)
#pragma unroll
            for (int q = 0; q < 4; q++) acc[i][j][q] = 0.0f;

    int l_row[4], l_c[4];
#pragma unroll
    for (int i = 0; i < 4; i++) {
        int slot = tid + i * 256;
        l_row[i] = slot >> 3;
        l_c[i] = slot & 7;
    }

    const unsigned as_base = (unsigned)__cvta_generic_to_shared(As);
    const unsigned bs_base = (unsigned)__cvta_generic_to_shared(Bs);
    const unsigned a_lane_off =
        ((wm + (lane & 7) + ((lane >> 3) & 1) * 8) * AW + ((lane >> 4) & 1) * 4) * 4;
    const unsigned b_lane_off =
        ((wn + (lane & 7) + ((lane >> 4) & 1) * 8) * AW + ((lane >> 3) & 1) * 4) * 4;

#define LOAD_TILE(k0, st)                                                          \
    do {                                                                           \
        unsigned* as = As + (st)*AS_WORDS;                                         \
        unsigned* bs = Bs + (st)*BS_WORDS;                                         \
        _Pragma("unroll") for (int i = 0; i < 4; i++) {                            \
            int row = l_row[i], c = l_c[i];                                        \
            int gr = bm + row;                                                     \
            cp16(as + row * AW + c * 4,                                            \
                 A + (size_t)gr * 512 + (k0) + c * 8, gr < M);                     \
            cp16(bs + row * AW + c * 4,                                            \
                 Wt + (size_t)(bn + row) * 512 + (k0) + c * 8, true);              \
        }                                                                          \
    } while (0)

    LOAD_TILE(0, 0);
    cp_commit();
    int stage = 0;
#pragma unroll 1
    for (int it = 0; it < 8; it++) {
        if (it + 1 < 8) {
            LOAD_TILE((it + 1) * 64, stage ^ 1);
            cp_commit();
            cp_wait<1>();
        } else {
            cp_wait<0>();
        }
        __syncthreads();
        const unsigned a_st = as_base + a_lane_off + stage * (AS_WORDS * 4);
        const unsigned b_st = bs_base + b_lane_off + stage * (BS_WORDS * 4);
#pragma unroll
        for (int ks = 0; ks < 4; ks++) {
            const unsigned kb = ks * 32;
            unsigned afr[2][4];
#pragma unroll
            for (int mt = 0; mt < 2; mt++)
                ldsm_x4(a_st + mt * (16 * AW * 4) + kb,
                        afr[mt][0], afr[mt][1], afr[mt][2], afr[mt][3]);
            unsigned bfr[8][2];
#pragma unroll
            for (int ntp = 0; ntp < 4; ntp++)
                ldsm_x4(b_st + ntp * (16 * AW * 4) + kb,
                        bfr[2 * ntp][0], bfr[2 * ntp][1],
                        bfr[2 * ntp + 1][0], bfr[2 * ntp + 1][1]);
#pragma unroll
            for (int mt = 0; mt < 2; mt++)
#pragma unroll
                for (int nt = 0; nt < 8; nt++)
                    mma_f16(acc[mt][nt], afr[mt], bfr[nt]);
        }
        __syncthreads();
        stage ^= 1;
    }

    __half* C = args.C[z];
    const float* rowscale = args.rs[z];
    const float* bias = args.b[z];
#pragma unroll
    for (int mt = 0; mt < 2; mt++) {
        int r0 = bm + wm + mt * 16 + g;
        int r1 = r0 + 8;
        float s0 = 1.0f, s1 = 1.0f;
        if (rowscale) {
            if (r0 < M) s0 = rowscale[r0];
            if (r1 < M) s1 = rowscale[r1];
        }
#pragma unroll
        for (int nt = 0; nt < 8; nt++) {
            int c = bn + wn + nt * 8 + t * 2;
            float b0 = 0.0f, b1 = 0.0f;
            if (bias) { b0 = bias[c]; b1 = bias[c + 1]; }
            if (r0 < M)
                *(__half2*)(C + (size_t)r0 * 512 + c) =
                    __floats2half2_rn(acc[mt][nt][0] * s0 + b0,
                                      acc[mt][nt][1] * s0 + b1);
            if (r1 < M)
                *(__half2*)(C + (size_t)r1 * 512 + c) =
                    __floats2half2_rn(acc[mt][nt][2] * s1 + b0,
                                      acc[mt][nt][3] * s1 + b1);
        }
    }
}

// ---------------- LN core ----------------
__device__ __forceinline__ float4 ln_elu_core4(
    float4 v, const float* __restrict__ gamma, const float* __restrict__ beta) {
    int t = threadIdx.x;
    float sum = v.x + v.y + v.z + v.w;
    sum = block_reduce_sum_128(sum);
    float u = sum * (1.0f / HH);
    float dx = v.x - u, dy = v.y - u, dz = v.z - u, dw = v.w - u;
    float var = dx * dx + dy * dy + dz * dz + dw * dw;
    var = block_reduce_sum_128(var) * (1.0f / HH);
    float inv = rsqrtf(var + 1e-12f);
    float4 ga = ((const float4*)gamma)[t];
    float4 be = ((const float4*)beta)[t];
    float y0 = ga.x * dx * inv + be.x;
    float y1 = ga.y * dy * inv + be.y;
    float y2 = ga.z * dz * inv + be.z;
    float y3 = ga.w * dw * inv + be.w;
    y0 = (y0 > 0.0f) ? y0 : (expf(y0) - 1.0f);
    y1 = (y1 > 0.0f) ? y1 : (expf(y1) - 1.0f);
    y2 = (y2 > 0.0f) ? y2 : (expf(y2) - 1.0f);
    y3 = (y3 > 0.0f) ? y3 : (expf(y3) - 1.0f);
    return make_float4(y0, y1, y2, y3);
}

__device__ __forceinline__ float4 load4h(const __half* p, int t) {
    uint2 raw = ((const uint2*)p)[t];
    float2 lo = __half22float2(*(__half2*)&raw.x);
    float2 hi = __half22float2(*(__half2*)&raw.y);
    return make_float4(lo.x, lo.y, hi.x, hi.y);
}

// ---------------- mega-fused per-node branch kernel (batched over r) ----------
__global__ __launch_bounds__(128) void fused_branches(
    const int* __restrict__ eid_all, const int* __restrict__ off_all,
    const int* __restrict__ src_all, const __half* __restrict__ go,
    const float* __restrict__ el_all, const float* __restrict__ er_all,
    const float* __restrict__ rdi_all,
    const float* __restrict__ bc_l, const float* __restrict__ gc_l,
    const float* __restrict__ bec_l,
    const float* __restrict__ bg_l, const float* __restrict__ gg_l,
    const float* __restrict__ beg_l,
    const float* __restrict__ bs_l, const float* __restrict__ gs_l,
    const float* __restrict__ bes_l,
    __half* __restrict__ out16) {
    const int n = blockIdx.x;
    const int r = blockIdx.y;
    const int* eid = eid_all + (size_t)r * EE;
    const int* off = off_all + (size_t)r * (NN + 1);
    const int* src = src_all + (size_t)r * EE;
    const __half* Xc = go + (size_t)(r * 3 + 0) * NNHH;
    const __half* f = go + (size_t)(r * 3 + 1) * NNHH;
    const __half* Xs = go + (size_t)(r * 3 + 2) * NNHH;
    const float* el = el_all + (size_t)r * NN * NHEADS;
    const float* er = er_all + (size_t)r * NN * NHEADS;
    const float* rdi = rdi_all + (size_t)r * NN;
    const float* bc = bc_l + r * HH;
    const float* gc = gc_l + r * HH;
    const float* bec = bec_l + r * HH;
    const float* bg = bg_l + r * HH;
    const float* gg = gg_l + r * HH;
    const float* beg = beg_l + r * HH;
    const float* bs_ = bs_l + r * HH;
    const float* gs = gs_l + r * HH;
    const float* bes = bes_l + r * HH;

    int p0 = off[n], p1 = off[n + 1];
    int t = threadIdx.x;
    int h = t >> 4;

    __shared__ float sh_m[NHEADS], sh_invs[NHEADS];
    if (t < NHEADS) {
        float ern = er[n * NHEADS + t];
        float mx = -INFINITY;
        for (int p = p0; p < p1; p++) {
            float x = el[src[eid[p]] * NHEADS + t] + ern;
            x = (x > 0.0f) ? x : 0.2f * x;
            mx = fmaxf(mx, x);
        }
        float s = 0.0f;
        for (int p = p0; p < p1; p++) {
            float x = el[src[eid[p]] * NHEADS + t] + ern;
            x = (x > 0.0f) ? x : 0.2f * x;
            s += expf(x - mx);
        }
        sh_m[t] = mx;
        sh_invs[t] = (s > 0.0f) ? (1.0f / s) : 1.0f;
    }
    __syncthreads();

    float mh = sh_m[h];
    float invs = sh_invs[h];
    float ern = er[n * NHEADS + h];

    float4 ac = make_float4(0.f, 0.f, 0.f, 0.f);
    float4 ag = make_float4(0.f, 0.f, 0.f, 0.f);
    for (int p = p0; p < p1; p++) {
        int e = eid[p];
        int sn = src[e];
        float4 rc = load4h(Xc + (size_t)sn * HH, t);
        float4 rg = load4h(f + (size_t)sn * HH, t);
        float x = el[sn * NHEADS + h] + ern;
        x = (x > 0.0f) ? x : 0.2f * x;
        float a = expf(x - mh) * invs;
        ac.x += rc.x; ac.y += rc.y; ac.z += rc.z; ac.w += rc.w;
        ag.x += a * rg.x; ag.y += a * rg.y; ag.z += a * rg.z; ag.w += a * rg.w;
    }

    float sc = rdi[n];
    float4 bb = ((const float4*)bc)[t];
    float4 v = make_float4(ac.x * sc + bb.x, ac.y * sc + bb.y,
                           ac.z * sc + bb.z, ac.w * sc + bb.w);
    float4 y = ln_elu_core4(v, gc, bec);
    float rx = y.x, ry = y.y, rz = y.z, rw = y.w;

    bb = ((const float4*)bg)[t];
    v = make_float4(ag.x + bb.x, ag.y + bb.y, ag.z + bb.z, ag.w + bb.w);
    y = ln_elu_core4(v, gg, beg);
    rx += y.x; ry += y.y; rz += y.z; rw += y.w;

    float4 xs = load4h(Xs + (size_t)n * HH, t);
    bb = ((const float4*)bs_)[t];
    v = make_float4(xs.x + bb.x, xs.y + bb.y, xs.z + bb.z, xs.w + bb.w);
    y = ln_elu_core4(v, gs, bes);
    rx += y.x; ry += y.y; rz += y.z; rw += y.w;

    __half2* op = (__half2*)(out16 + (size_t)n * (RR * HH) + (size_t)r * HH + 4 * t);
    op[0] = __floats2half2_rn(rx, ry);
    op[1] = __floats2half2_rn(rz, rw);
}

// ---------------- GAT attn-score precompute (batched over r) ----------------
__global__ void gat_el_er(const __half* __restrict__ go,
                          const float* __restrict__ al_l,
                          const float* __restrict__ ar_l,
                          float* __restrict__ el_all, float* __restrict__ er_all) {
    int idx = blockIdx.x * blockDim.x + threadIdx.x;
    if (idx >= NN * NHEADS) return;
    int r = blockIdx.y;
    int n = idx >> 3;
    int hh = idx & 7;
    const __half* f = go + (size_t)(r * 3 + 1) * NNHH;
    const __half* fr = f + (size_t)n * HH + hh * DHH;
    const float* a1 = al_l + r * NHEADS * DHH + hh * DHH;
    const float* a2 = ar_l + r * NHEADS * DHH + hh * DHH;
    float s1 = 0.0f, s2 = 0.0f;
#pragma unroll 8
    for (int d = 0; d < DHH; d++) {
        float fv = __half2float(fr[d]);
        s1 += fv * a1[d];
        s2 += fv * a2[d];
    }
    el_all[(size_t)r * NN * NHEADS + idx] = s1;
    er_all[(size_t)r * NN * NHEADS + idx] = s2;
}

// ---------------- relation MHA (3 tokens) + mean ----------------
__global__ __launch_bounds__(256) void mha_mean(
    const __half* __restrict__ q, const __half* __restrict__ k,
    const __half* __restrict__ v, float* __restrict__ out,
    __half* __restrict__ out16) {
    int n = blockIdx.x;
    int hd = threadIdx.x >> 5;
    int lane = threadIdx.x & 31;
    size_t base = (size_t)n * RR * HH + hd * DHH;
    float qa[RR], qb[RR], ka[RR], kb[RR], va[RR], vb[RR];
#pragma unroll
    for (int r = 0; r < RR; r++) {
        size_t off = base + (size_t)r * HH;
        qa[r] = __half2float(q[off + lane]);
        qb[r] = __half2float(q[off + lane + 32]);
        ka[r] = __half2float(k[off + lane]);
        kb[r] = __half2float(k[off + lane + 32]);
        va[r] = __half2float(v[off + lane]);
        vb[r] = __half2float(v[off + lane + 32]);
    }
    float sc[RR][RR];
#pragma unroll
    for (int r = 0; r < RR; r++)
#pragma unroll
        for (int t = 0; t < RR; t++) {
            float p = qa[r] * ka[t] + qb[r] * kb[t];
#pragma unroll
            for (int o = 16; o > 0; o >>= 1) p += __shfl_xor_sync(0xffffffffu, p, o);
            sc[r][t] = p * 0.125f;
        }
    float w0 = 0.0f, w1 = 0.0f, w2 = 0.0f;
#pragma unroll
    for (int r = 0; r < RR; r++) {
        float mx = fmaxf(sc[r][0], fmaxf(sc[r][1], sc[r][2]));
        float e0 = expf(sc[r][0] - mx);
        float e1 = expf(sc[r][1] - mx);
        float e2 = expf(sc[r][2] - mx);
        float inv = 1.0f / (e0 + e1 + e2);
        w0 += e0 * inv;
        w1 += e1 * inv;
        w2 += e2 * inv;
    }
    const float third = 1.0f / 3.0f;
    float oa = (w0 * va[0] + w1 * va[1] + w2 * va[2]) * third;
    float ob = (w0 * vb[0] + w1 * vb[1] + w2 * vb[2]) * third;
    size_t o0 = (size_t)n * HH + hd * DHH + lane;
    out[o0] = oa;
    out[o0 + 32] = ob;
    out16[o0] = __float2half_rn(oa);
    out16[o0 + 32] = __float2half_rn(ob);
}

// ---------------- classifier ----------------
__global__ void classify(const float* __restrict__ h, const float* __restrict__ W,
                         const float* __restrict__ b, float* __restrict__ out) {
    int idx = blockIdx.x * blockDim.x + threadIdx.x;
    if (idx >= NN * NCLSS) return;
    int n = idx / NCLSS;
    int c = idx % NCLSS;
    const float* hr = h + (size_t)n * HH;
    float sum = b[c];
#pragma unroll 8
    for (int j = 0; j < HH; j++) sum += hr[j] * W[j * NCLSS + c];
    out[idx] = sum;
}

// ---------------- launch ----------------
extern "C" void kernel_launch(void* const* d_in, const int* in_sizes, int n_in,
                              void* d_out, int out_size) {
    const float* feature = (const float*)d_in[0];
    const int* src = (const int*)d_in[1];
    const int* dst = (const int*)d_in[2];
    const float* Wc = (const float*)d_in[3];
    const float* bc = (const float*)d_in[4];
    const float* gc = (const float*)d_in[5];
    const float* betac = (const float*)d_in[6];
    const float* Wg = (const float*)d_in[7];
    const float* bg = (const float*)d_in[8];
    const float* al = (const float*)d_in[9];
    const float* ar = (const float*)d_in[10];
    const float* gg = (const float*)d_in[11];
    const float* betag = (const float*)d_in[12];
    const float* Ws = (const float*)d_in[13];
    const float* bs = (const float*)d_in[14];
    const float* gs = (const float*)d_in[15];
    const float* betas = (const float*)d_in[16];
    const float* Wq = (const float*)d_in[17];
    const float* bq = (const float*)d_in[18];
    const float* Wk = (const float*)d_in[19];
    const float* bk = (const float*)d_in[20];
    const float* Wv = (const float*)d_in[21];
    const float* bv = (const float*)d_in[22];
    const float* Wout = (const float*)d_in[23];
    const float* bout = (const float*)d_in[24];
    float* out = (float*)d_out;

    float *p_h, *p_rdo, *p_rdi, *p_el, *p_er;
    __half *p_h16, *p_go16, *p_stk16, *p_w16, *p_q, *p_k, *p_v;
    int *p_cnt, *p_cur, *p_off, *p_eid;
    cudaGetSymbolAddress((void**)&p_h, g_h);
    cudaGetSymbolAddress((void**)&p_h16, g_h16);
    cudaGetSymbolAddress((void**)&p_go16, g_go16);
    cudaGetSymbolAddress((void**)&p_stk16, g_stk16);
    cudaGetSymbolAddress((void**)&p_q, g_q);
    cudaGetSymbolAddress((void**)&p_k, g_k);
    cudaGetSymbolAddress((void**)&p_v, g_v);
    cudaGetSymbolAddress((void**)&p_w16, g_w16);
    cudaGetSymbolAddress((void**)&p_rdo, g_rdo);
    cudaGetSymbolAddress((void**)&p_rdi, g_rdi);
    cudaGetSymbolAddress((void**)&p_el, g_el);
    cudaGetSymbolAddress((void**)&p_er, g_er);
    cudaGetSymbolAddress((void**)&p_cnt, g_cnt);
    cudaGetSymbolAddress((void**)&p_cur, g_cur);
    cudaGetSymbolAddress((void**)&p_off, g_off);
    cudaGetSymbolAddress((void**)&p_eid, g_eid);

    cudaFuncSetAttribute(f16gemm9, cudaFuncAttributeMaxDynamicSharedMemorySize,
                         GEMM_SMEM);

    const size_t WHH = (size_t)HH * HH;
    __half* w16_Wc = p_w16;
    __half* w16_Wg = p_w16 + 6 * WHH;
    __half* w16_Ws = p_w16 + 12 * WHH;
    __half* w16_Wq = p_w16 + 18 * WHH;
    __half* w16_Wk = p_w16 + 20 * WHH;
    __half* w16_Wv = p_w16 + 22 * WHH;

    {
        dim3 tb(32, 8);
        transpose_cvt16<<<dim3(16, 16, 6), tb>>>(Wc, w16_Wc);
        transpose_cvt16<<<dim3(16, 16, 6), tb>>>(Wg, w16_Wg);
        transpose_cvt16<<<dim3(16, 16, 6), tb>>>(Ws, w16_Ws);
        transpose_cvt16<<<dim3(16, 16, 2), tb>>>(Wq, w16_Wq);
        transpose_cvt16<<<dim3(16, 16, 2), tb>>>(Wk, w16_Wk);
        transpose_cvt16<<<dim3(16, 16, 2), tb>>>(Wv, w16_Wv);
        int n4f = (int)(NNHH / 4);
        cvt_f16_vec<<<(n4f + 255) / 256, 256>>>((const float4*)feature,
                                                (__half2*)p_h16, n4f);
    }

    cudaMemsetAsync(p_rdo, 0, (size_t)RR * NN * sizeof(float), 0);
    cudaMemsetAsync(p_rdi, 0, (size_t)RR * NN * sizeof(float), 0);
    cudaMemsetAsync(p_cnt, 0, (size_t)RR * NN * sizeof(int), 0);
    cudaMemsetAsync(p_cur, 0, (size_t)RR * NN * sizeof(int), 0);
    degree_count<<<(RR * EE + 255) / 256, 256>>>(src, dst, p_rdo, p_rdi, p_cnt);
    degree_finalize<<<(RR * NN + 255) / 256, 256>>>(p_rdo, RR * NN);
    degree_finalize<<<(RR * NN + 255) / 256, 256>>>(p_rdi, RR * NN);
    scan_offsets<<<RR, 1024>>>(p_cnt, p_off);
    build_adj<<<(RR * EE + 255) / 256, 256>>>(dst, p_off, p_cur, p_eid);

    const dim3 gemm_grid_n(4, (NN + 127) / 128, 9);
    const dim3 gemm_grid_nr(4, (NN * RR + 127) / 128, 3);
    const dim3 elgrid((NN * NHEADS + 255) / 256, 3);
    const dim3 fgrid(NN, 3);

    for (int l = 0; l < LL; l++) {
        const size_t lbase = (size_t)l * RR;

        G9 a9;
        for (int r = 0; r < RR; r++) {
            const size_t lr = lbase + r;
            a9.W[r * 3 + 0] = w16_Wc + lr * WHH;
            a9.W[r * 3 + 1] = w16_Wg + lr * WHH;
            a9.W[r * 3 + 2] = w16_Ws + lr * WHH;
            for (int bI = 0; bI < 3; bI++) {
                a9.C[r * 3 + bI] = p_go16 + (size_t)(r * 3 + bI) * NNHH;
                a9.b[r * 3 + bI] = nullptr;
            }
            a9.rs[r * 3 + 0] = p_rdo + (size_t)r * NN;
            a9.rs[r * 3 + 1] = nullptr;
            a9.rs[r * 3 + 2] = nullptr;
        }
        f16gemm9<<<gemm_grid_n, 256, GEMM_SMEM>>>(p_h16, a9, NN);

        gat_el_er<<<elgrid, 256>>>(p_go16, al + lbase * NHEADS * DHH,
                                   ar + lbase * NHEADS * DHH, p_el, p_er);
        fused_branches<<<fgrid, 128>>>(
            p_eid, p_off, src, p_go16, p_el, p_er, p_rdi,
            bc + lbase * HH, gc + lbase * HH, betac + lbase * HH,
            bg + lbase * HH, gg + lbase * HH, betag + lbase * HH,
            bs + lbase * HH, gs + lbase * HH, betas + lbase * HH,
            p_stk16);

        G9 aq;
        aq.W[0] = w16_Wq + (size_t)l * WHH;
        aq.W[1] = w16_Wk + (size_t)l * WHH;
        aq.W[2] = w16_Wv + (size_t)l * WHH;
        aq.C[0] = p_q;
        aq.C[1] = p_k;
        aq.C[2] = p_v;
        aq.rs[0] = nullptr; aq.rs[1] = nullptr; aq.rs[2] = nullptr;
        aq.b[0] = bq + (size_t)l * HH;
        aq.b[1] = bk + (size_t)l * HH;
        aq.b[2] = bv + (size_t)l * HH;
        for (int zz = 3; zz < 9; zz++) {
            aq.W[zz] = nullptr; aq.C[zz] = nullptr;
            aq.rs[zz] = nullptr; aq.b[zz] = nullptr;
        }
        f16gemm9<<<gemm_grid_nr, 256, GEMM_SMEM>>>(p_stk16, aq, NN * RR);

        mha_mean<<<NN, 256>>>(p_q, p_k, p_v, p_h, p_h16);
    }

    classify<<<(NN * NCLSS + 255) / 256, 256>>>(p_h, Wout, bout, out);
}